// round 6
// baseline (speedup 1.0000x reference)
#include <cuda_runtime.h>
#include <cuda_fp16.h>
#include <math.h>
#include <stdint.h>

// ===========================================================================
// Scratch (device globals; no allocation allowed)
// B=4, S=4096, D=512 -> M = 16384
// ===========================================================================
#define MAXELEM (16384 * 512)
#define MAXPH   (4096 * 512)
#define WELEM   (512 * 512)

__device__ __align__(256) __half g_h[7][MAXELEM];    // xh,Kh,Qh,NBh,KMh,QMh,Vh
__device__ __align__(256) __half g_wh[6][WELEM];     // 6 fp16 weights
__device__ float g_cb[MAXPH];
__device__ float g_sb[MAXPH];

// ===========================================================================
// helpers
// ===========================================================================
__device__ __forceinline__ uint32_t smem_to_u32(const void* smem_ptr) {
    uint32_t addr;
    asm("{ .reg .u64 tmp; cvta.to.shared.u64 tmp, %1; cvt.u32.u64 %0, tmp; }"
        : "=r"(addr) : "l"(smem_ptr));
    return addr;
}

__device__ __forceinline__ void ldsm_x4(uint32_t& r0, uint32_t& r1,
                                        uint32_t& r2, uint32_t& r3, uint32_t a) {
    asm volatile("ldmatrix.sync.aligned.m8n8.x4.shared.b16 {%0,%1,%2,%3}, [%4];\n"
                 : "=r"(r0), "=r"(r1), "=r"(r2), "=r"(r3) : "r"(a));
}

__device__ __forceinline__ void mma16816(float* c, const uint32_t* a,
                                         const uint32_t* b) {
    asm volatile(
        "mma.sync.aligned.m16n8k16.row.col.f32.f16.f16.f32 "
        "{%0,%1,%2,%3},{%4,%5,%6,%7},{%8,%9},{%0,%1,%2,%3};\n"
        : "+f"(c[0]), "+f"(c[1]), "+f"(c[2]), "+f"(c[3])
        : "r"(a[0]), "r"(a[1]), "r"(a[2]), "r"(a[3]), "r"(b[0]), "r"(b[1]));
}

// ===========================================================================
// base-phase cos/sin table
// ===========================================================================
__global__ void phase_table_kernel(const float* __restrict__ bp,
                                   float* __restrict__ cb,
                                   float* __restrict__ sb, int n) {
    int i = blockIdx.x * blockDim.x + threadIdx.x;
    if (i < n) {
        float s, c;
        sincosf(bp[i], &s, &c);
        cb[i] = c;
        sb[i] = s;
    }
}

// ===========================================================================
// fp32 -> fp16 converters
// ===========================================================================
__global__ void tohalf_kernel(const float4* __restrict__ src,
                              __half2* __restrict__ dst, int n4) {
    int i = blockIdx.x * blockDim.x + threadIdx.x;
    if (i < n4) {
        float4 v = src[i];
        dst[2 * i + 0] = __floats2half2_rn(v.x, v.y);
        dst[2 * i + 1] = __floats2half2_rn(v.z, v.w);
    }
}

__global__ void tohalf3_kernel(const float4* s0, const float4* s1,
                               const float4* s2, __half2* d0, __half2* d1,
                               __half2* d2, int n4) {
    int i = blockIdx.x * blockDim.x + threadIdx.x;
    if (i >= 3 * n4) return;
    int t = i / n4, j = i - t * n4;
    const float4* s = (t == 0) ? s0 : (t == 1) ? s1 : s2;
    __half2* d = (t == 0) ? d0 : (t == 1) ? d1 : d2;
    float4 v = s[j];
    d[2 * j + 0] = __floats2half2_rn(v.x, v.y);
    d[2 * j + 1] = __floats2half2_rn(v.z, v.w);
}

// ===========================================================================
// fp16 HMMA GEMM (NT), batched via blockIdx.z job select.
// CTA tile 128x128, KC=64. 128 threads = 4 warps in 2x2 grid, each warp
// computes 64x64 (square tile -> minimal smem crossbar traffic per MMA).
// 3-stage cp.async ring, one __syncthreads per chunk, prefetch distance 2.
// mode 1: outH = fp16(acc + bias)
// mode 2: outF = acc + bias + resid
// ===========================================================================
#define KC 64
#define ROWB 144
#define TILE_B (128 * ROWB)
#define STAGE_B (2 * TILE_B)          // 36864
#define NSTAGE 3
#define GEMM_SMEM (NSTAGE * STAGE_B)  // 110592

struct Job {
    const __half* A;
    const __half* W;
    const float*  bias;
    const float*  resid;
    float*        outF;
    __half*       outH;
    int           mode;
};

__global__ __launch_bounds__(128, 2) void gemm_h(
    Job j0, Job j1, Job j2, int M, int N, int K)
{
    extern __shared__ char smem[];
    const Job jb = (blockIdx.z == 0) ? j0 : (blockIdx.z == 1) ? j1 : j2;

    const uint32_t sbase = smem_to_u32(smem);
    const int tid = threadIdx.x;
    const int wid = tid >> 5, lane = tid & 31;
    const int bm = blockIdx.y * 128;
    const int bn = blockIdx.x * 128;
    const int wm = wid >> 1, wn = wid & 1;   // 2x2 warp grid, 64x64 tiles
    const int NCH = K / KC;

    const __half* Ab = jb.A + (size_t)bm * K;
    const __half* Wb = jb.W + (size_t)bn * K;

    auto load_chunk = [&](int kc, int s) {
        uint32_t st = sbase + s * STAGE_B;
        int koff = kc * KC;
        #pragma unroll
        for (int j = 0; j < 16; j++) {
            int q = tid + j * 128;           // 0..2047
            int t = q >> 10;                 // 0 = A tile, 1 = W tile
            int r = (q >> 3) & 127;
            int seg = q & 7;
            const __half* src = (t ? Wb : Ab) + (size_t)r * K + koff + seg * 8;
            uint32_t dst = st + t * TILE_B + r * ROWB + seg * 16;
            asm volatile("cp.async.cg.shared.global [%0], [%1], 16;\n"
                         :: "r"(dst), "l"(src));
        }
        asm volatile("cp.async.commit_group;\n");
    };

    float acc[4][8][4];
    #pragma unroll
    for (int i = 0; i < 4; i++)
        #pragma unroll
        for (int j = 0; j < 8; j++)
            #pragma unroll
            for (int e = 0; e < 4; e++) acc[i][j][e] = 0.f;

    load_chunk(0, 0);
    load_chunk(1, 1);

    const uint32_t a_r = (lane & 15);
    const uint32_t a_k = (lane >> 4) * 16;
    const uint32_t b_r = (lane & 7) + ((lane >> 4) << 3);
    const uint32_t b_k = ((lane >> 3) & 1) * 16;

    for (int i = 0; i < NCH; i++) {
        int s = i % NSTAGE;
        if (i == NCH - 1)
            asm volatile("cp.async.wait_group 0;\n" ::: "memory");
        else
            asm volatile("cp.async.wait_group 1;\n" ::: "memory");
        __syncthreads();
        if (i + 2 < NCH) load_chunk(i + 2, (i + 2) % NSTAGE);

        uint32_t At = sbase + s * STAGE_B;
        uint32_t Wt = At + TILE_B;

        #pragma unroll
        for (int k16 = 0; k16 < 4; k16++) {
            uint32_t a[4][4];
            #pragma unroll
            for (int mi = 0; mi < 4; mi++) {
                uint32_t addr = At + (wm * 64 + mi * 16 + a_r) * ROWB
                              + k16 * 32 + a_k;
                ldsm_x4(a[mi][0], a[mi][1], a[mi][2], a[mi][3], addr);
            }
            uint32_t b[8][2];
            #pragma unroll
            for (int bp = 0; bp < 4; bp++) {
                uint32_t r0, r1, r2, r3;
                uint32_t addr = Wt + (wn * 64 + bp * 16 + b_r) * ROWB
                              + k16 * 32 + b_k;
                ldsm_x4(r0, r1, r2, r3, addr);
                b[2 * bp + 0][0] = r0; b[2 * bp + 0][1] = r1;
                b[2 * bp + 1][0] = r2; b[2 * bp + 1][1] = r3;
            }
            #pragma unroll
            for (int mi = 0; mi < 4; mi++)
                #pragma unroll
                for (int ni = 0; ni < 8; ni++)
                    mma16816(acc[mi][ni], a[mi], b[ni]);
        }
    }

    // epilogue
    const int r0 = bm + wm * 64 + (lane >> 2);
    const int c0 = bn + wn * 64 + (lane & 3) * 2;
    const int mode = jb.mode;
    #pragma unroll
    for (int mi = 0; mi < 4; mi++) {
        #pragma unroll
        for (int h = 0; h < 2; h++) {
            int row = r0 + mi * 16 + h * 8;
            #pragma unroll
            for (int ni = 0; ni < 8; ni++) {
                int col = c0 + ni * 8;
                size_t idx = (size_t)row * N + col;
                float2 bv = *(const float2*)(jb.bias + col);
                float v0 = acc[mi][ni][2 * h + 0] + bv.x;
                float v1 = acc[mi][ni][2 * h + 1] + bv.y;
                if (mode == 2) {
                    float2 rv = *(const float2*)(jb.resid + idx);
                    v0 += rv.x; v1 += rv.y;
                    float2 o; o.x = v0; o.y = v1;
                    *(float2*)(jb.outF + idx) = o;
                } else {
                    *(__half2*)(jb.outH + idx) = __floats2half2_rn(v0, v1);
                }
            }
        }
    }
}

// ===========================================================================
// Taylor sincos for tiny delta
// ===========================================================================
__device__ __forceinline__ void sincos_small(float x, float& s, float& c) {
    float x2 = x * x;
    s = x * fmaf(x2, fmaf(x2, fmaf(x2, -1.f / 5040.f, 1.f / 120.f), -1.f / 6.f), 1.f);
    c = fmaf(x2, fmaf(x2, fmaf(x2, -1.f / 720.f, 1.f / 24.f), -0.5f), 1.f);
}

// ===========================================================================
// Fused phasor bind + chunked cumsum + retrieval + LayerNorm -> fp16.
// Block = one (batch, chunk), 512 threads = one per feature d. Two barriers.
// ===========================================================================
#define CHK 64
#define NW  16

__global__ __launch_bounds__(512) void phasor_ln_kernel(
    const __half* __restrict__ V, const __half* __restrict__ KM,
    const __half* __restrict__ QM,
    const float* __restrict__ cb, const float* __restrict__ sbt,
    const float* __restrict__ msp,
    const float* __restrict__ lng, const float* __restrict__ lnb,
    __half* __restrict__ Oh, int S, int D)
{
    const int d = threadIdx.x;
    const int nC = S / CHK;
    const int b = blockIdx.x / nC;
    const int c = blockIdx.x % nC;

    const float ms  = msp[0];
    const float g   = lng[d];
    const float be  = lnb[d];
    const float inv = rsqrtf((float)D);

    const int lane = d & 31;
    const int w    = d >> 5;

    __shared__ float sm1[CHK * 17];
    __shared__ float sm2[CHK * 17];
    __shared__ float smu[CHK];
    __shared__ float srs[CHK];

    float r[CHK];
    float mr = 0.f, mi = 0.f;
    size_t base  = ((size_t)b * S + (size_t)c * CHK) * D + d;
    size_t pbase = ((size_t)c * CHK) * D + d;

    #pragma unroll
    for (int s = 0; s < CHK; s++) {
        size_t idx  = base + (size_t)s * D;
        size_t pidx = pbase + (size_t)s * D;

        float cbp = cb[pidx];
        float sbp = sbt[pidx];
        float dk = __half2float(KM[idx]) * ms;
        float dq = __half2float(QM[idx]) * ms;
        float sk, ck, sq, cq;
        sincos_small(dk, sk, ck);
        sincos_small(dq, sq, cq);

        float ckp = cbp * ck - sbp * sk;
        float skp = sbp * ck + cbp * sk;
        float cqp = cbp * cq - sbp * sq;
        float sqp = sbp * cq + cbp * sq;

        float v = __half2float(V[idx]);
        mr = fmaf(v, ckp, mr);
        mi = fmaf(v, skp, mi);

        float rv = (mr * cqp + mi * sqp) * inv;
        r[s] = rv;

        float s1 = rv, s2 = rv * rv;
        #pragma unroll
        for (int o = 16; o > 0; o >>= 1) {
            s1 += __shfl_xor_sync(0xffffffffu, s1, o);
            s2 += __shfl_xor_sync(0xffffffffu, s2, o);
        }
        if (lane == 0) { sm1[s * 17 + w] = s1; sm2[s * 17 + w] = s2; }
    }
    __syncthreads();

    if (d < CHK) {
        float a1 = 0.f, a2 = 0.f;
        #pragma unroll
        for (int j = 0; j < NW; j++) {
            a1 += sm1[d * 17 + j];
            a2 += sm2[d * 17 + j];
        }
        float mu = a1 / (float)D;
        smu[d] = mu;
        srs[d] = rsqrtf(a2 / (float)D - mu * mu + 1e-5f);
    }
    __syncthreads();

    #pragma unroll
    for (int s = 0; s < CHK; s++) {
        float normed = (r[s] - smu[s]) * srs[s] * g + be;
        Oh[base + (size_t)s * D] = __float2half(normed);
    }
}

// ===========================================================================
// Launch
// ===========================================================================
extern "C" void kernel_launch(void* const* d_in, const int* in_sizes, int n_in,
                              void* d_out, int out_size)
{
    const float* x    = (const float*)d_in[0];
    const float* bp   = (const float*)d_in[1];
    const float* Wk   = (const float*)d_in[2];
    const float* bk   = (const float*)d_in[3];
    const float* Wv   = (const float*)d_in[4];
    const float* bv   = (const float*)d_in[5];
    const float* Wq   = (const float*)d_in[6];
    const float* bq   = (const float*)d_in[7];
    const float* Wkm  = (const float*)d_in[8];
    const float* bkm  = (const float*)d_in[9];
    const float* Wqm  = (const float*)d_in[10];
    const float* bqm  = (const float*)d_in[11];
    const float* ms   = (const float*)d_in[12];
    const float* lng  = (const float*)d_in[13];
    const float* lnb  = (const float*)d_in[14];
    const float* Wo   = (const float*)d_in[15];
    const float* bo   = (const float*)d_in[16];
    float* out = (float*)d_out;

    const int D  = in_sizes[3];         // 512
    const int SD = in_sizes[1];         // S*D
    const int S  = SD / D;              // 4096
    const int M  = in_sizes[0] / D;     // 16384

    __half* hp = nullptr;   cudaGetSymbolAddress((void**)&hp, g_h);
    __half* whp = nullptr;  cudaGetSymbolAddress((void**)&whp, g_wh);
    float* cbuf = nullptr;  cudaGetSymbolAddress((void**)&cbuf, g_cb);
    float* sbuf = nullptr;  cudaGetSymbolAddress((void**)&sbuf, g_sb);

    __half* xh  = hp + 0L * MAXELEM;
    __half* Kh  = hp + 1L * MAXELEM;
    __half* Qh  = hp + 2L * MAXELEM;
    __half* NBh = hp + 3L * MAXELEM;
    __half* KMh = hp + 4L * MAXELEM;
    __half* QMh = hp + 5L * MAXELEM;
    __half* Vh  = hp + 6L * MAXELEM;

    __half* Wh[6];
    for (int j = 0; j < 6; j++) Wh[j] = whp + (size_t)j * WELEM;

    cudaFuncSetAttribute(gemm_h, cudaFuncAttributeMaxDynamicSharedMemorySize,
                         GEMM_SMEM);

    const int W4 = WELEM / 4;

    // 0: x -> fp16
    tohalf_kernel<<<(M * D / 4 + 255) / 256, 256>>>(
        (const float4*)x, (__half2*)xh, M * D / 4);
    // 1: Wk, Wv, Wq -> fp16
    tohalf3_kernel<<<(3 * W4 + 255) / 256, 256>>>(
        (const float4*)Wk, (const float4*)Wv, (const float4*)Wq,
        (__half2*)Wh[0], (__half2*)Wh[1], (__half2*)Wh[2], W4);
    // 2: Wkm, Wqm, Wo -> fp16
    tohalf3_kernel<<<(3 * W4 + 255) / 256, 256>>>(
        (const float4*)Wkm, (const float4*)Wqm, (const float4*)Wo,
        (__half2*)Wh[3], (__half2*)Wh[4], (__half2*)Wh[5], W4);

    dim3 g3(D / 128, M / 128, 3);
    dim3 g2(D / 128, M / 128, 2);
    dim3 g1(D / 128, M / 128, 1);

    Job jK  = { xh,  Wh[0], bk,  nullptr, nullptr, Kh,  1 };
    Job jV  = { xh,  Wh[1], bv,  nullptr, nullptr, Vh,  1 };
    Job jQ  = { xh,  Wh[2], bq,  nullptr, nullptr, Qh,  1 };
    Job jKM = { Kh,  Wh[3], bkm, nullptr, nullptr, KMh, 1 };
    Job jQM = { Qh,  Wh[4], bqm, nullptr, nullptr, QMh, 1 };
    Job jO  = { NBh, Wh[5], bo,  x,       out,     nullptr, 2 };

    // 3: K, V, Q  (ncu -s 5 lands here)
    gemm_h<<<g3, 128, GEMM_SMEM>>>(jK, jV, jQ, M, D, D);
    // 4: phase table
    phase_table_kernel<<<(SD + 255) / 256, 256>>>(bp, cbuf, sbuf, SD);
    // 5: KM, QM
    gemm_h<<<g2, 128, GEMM_SMEM>>>(jKM, jQM, jQM, M, D, D);
    // 6: phasor + cumsum + retrieval + LayerNorm
    phasor_ln_kernel<<<(M / CHK), D>>>(Vh, KMh, QMh, cbuf, sbuf, ms, lng, lnb,
                                       NBh, S, D);
    // 7: out = x + normed@Wo^T + bo
    gemm_h<<<g1, 128, GEMM_SMEM>>>(jO, jO, jO, M, D, D);
}

// round 7
// speedup vs baseline: 1.3267x; 1.3267x over previous
#include <cuda_runtime.h>
#include <cuda_fp16.h>
#include <math.h>
#include <stdint.h>

// ===========================================================================
// Scratch (device globals; no allocation allowed)
// B=4, S=4096, D=512 -> M = 16384
// ===========================================================================
#define MAXELEM (16384 * 512)
#define MAXPH   (4096 * 512)
#define WELEM   (512 * 512)

__device__ __align__(256) __half g_h[5][MAXELEM];    // xh, NBh, KMh, QMh, Vh
__device__ __align__(256) __half g_wh[10][WELEM];    // Wk..Wo, WkT, WqT, Wc_km, Wc_qm
__device__ float g_cb[MAXPH];
__device__ float g_sb[MAXPH];
__device__ float g_bc[2][512];                       // composite biases
__device__ float g_zero[512];                        // stays zero (.bss)

// ===========================================================================
// helpers
// ===========================================================================
__device__ __forceinline__ uint32_t smem_to_u32(const void* smem_ptr) {
    uint32_t addr;
    asm("{ .reg .u64 tmp; cvta.to.shared.u64 tmp, %1; cvt.u32.u64 %0, tmp; }"
        : "=r"(addr) : "l"(smem_ptr));
    return addr;
}

__device__ __forceinline__ void ldsm_x4(uint32_t& r0, uint32_t& r1,
                                        uint32_t& r2, uint32_t& r3, uint32_t a) {
    asm volatile("ldmatrix.sync.aligned.m8n8.x4.shared.b16 {%0,%1,%2,%3}, [%4];\n"
                 : "=r"(r0), "=r"(r1), "=r"(r2), "=r"(r3) : "r"(a));
}

__device__ __forceinline__ void mma16816(float* c, const uint32_t* a,
                                         const uint32_t* b) {
    asm volatile(
        "mma.sync.aligned.m16n8k16.row.col.f32.f16.f16.f32 "
        "{%0,%1,%2,%3},{%4,%5,%6,%7},{%8,%9},{%0,%1,%2,%3};\n"
        : "+f"(c[0]), "+f"(c[1]), "+f"(c[2]), "+f"(c[3])
        : "r"(a[0]), "r"(a[1]), "r"(a[2]), "r"(a[3]), "r"(b[0]), "r"(b[1]));
}

// ===========================================================================
// Launch 0: convert x + 6 weights fp32 -> fp16 in one kernel.
// blocks [0, XB)        -> x          (XB = M*D/4/256)
// blocks [XB, XB+6*WB)  -> weights    (WB = WELEM/4/256)
// ===========================================================================
struct CvtArgs {
    const float4* x;
    const float4* w[6];
    __half2* xh;
    __half2* wh[6];
    int x4;   // M*D/4
    int w4;   // WELEM/4
};

__global__ void tohalf_all(CvtArgs a) {
    int i = blockIdx.x * blockDim.x + threadIdx.x;
    const float4* s;
    __half2* d;
    int j;
    if (i < a.x4) {
        s = a.x; d = a.xh; j = i;
    } else {
        int q = i - a.x4;
        int t = q / a.w4;
        j = q - t * a.w4;
        s = a.w[t]; d = a.wh[t];
    }
    float4 v = s[j];
    d[2 * j + 0] = __floats2half2_rn(v.x, v.y);
    d[2 * j + 1] = __floats2half2_rn(v.z, v.w);
}

// ===========================================================================
// Launch 1: prep — transpose Wk,Wq (fp16) + composite biases.
// blocks [0,256): WkT tiles, [256,512): WqT tiles,
// blocks [512,576): bc_km rows, [576,640): bc_qm rows.
// ===========================================================================
__global__ void prep_kernel(
    const __half* __restrict__ Wk_h, const __half* __restrict__ Wq_h,
    __half* __restrict__ WkT, __half* __restrict__ WqT,
    const float* __restrict__ Wkm, const float* __restrict__ Wqm,
    const float* __restrict__ bk,  const float* __restrict__ bq,
    const float* __restrict__ bkm, const float* __restrict__ bqm,
    float* __restrict__ bckm, float* __restrict__ bcqm)
{
    int blk = blockIdx.x;
    int t = threadIdx.x;
    if (blk < 512) {
        __shared__ __half sm[32][33];
        const __half* src = (blk < 256) ? Wk_h : Wq_h;
        __half* dst = (blk < 256) ? WkT : WqT;
        int idx = blk & 255;
        int tr = idx >> 4, tc = idx & 15;
        int tx = t & 31, ty = t >> 5;         // 32 x 8
        #pragma unroll
        for (int i = 0; i < 4; i++) {
            int r = tr * 32 + ty + i * 8;
            int c = tc * 32 + tx;
            sm[ty + i * 8][tx] = src[r * 512 + c];
        }
        __syncthreads();
        #pragma unroll
        for (int i = 0; i < 4; i++) {
            int r = tc * 32 + ty + i * 8;
            int c = tr * 32 + tx;
            dst[r * 512 + c] = sm[tx][ty + i * 8];
        }
    } else {
        // composite bias: bc[i] = bm2[i] + sum_j Wm[i,j] * b1[j]
        int isQ = (blk >= 576);
        const float* Wm = isQ ? Wqm : Wkm;
        const float* b1 = isQ ? bq  : bk;
        const float* b2 = isQ ? bqm : bkm;
        float* bc = isQ ? bcqm : bckm;
        int rb = (blk - (isQ ? 576 : 512)) * 8;
        int wid = t >> 5, lane = t & 31;
        int row = rb + wid;
        float s = 0.f;
        #pragma unroll
        for (int j = 0; j < 16; j++)
            s += Wm[row * 512 + lane + 32 * j] * b1[lane + 32 * j];
        #pragma unroll
        for (int o = 16; o > 0; o >>= 1)
            s += __shfl_xor_sync(0xffffffffu, s, o);
        if (lane == 0) bc[row] = s + b2[row];
    }
}

// ===========================================================================
// fp16 HMMA GEMM (NT), batched via blockIdx.z job select.
// CTA tile 128x128, KC=64, 256 threads (8 warps 2x4, each 64x32),
// 3-stage cp.async ring, one __syncthreads per chunk. [R5 config — best measured]
// mode 1: outH = fp16(acc + bias)
// mode 2: outF = acc + bias + resid
// ===========================================================================
#define KC 64
#define ROWB 144
#define TILE_B (128 * ROWB)
#define STAGE_B (2 * TILE_B)          // 36864
#define NSTAGE 3
#define GEMM_SMEM (NSTAGE * STAGE_B)  // 110592

struct Job {
    const __half* A;
    const __half* W;
    const float*  bias;
    const float*  resid;
    float*        outF;
    __half*       outH;
    int           mode;
};

__global__ __launch_bounds__(256, 2) void gemm_h(
    Job j0, Job j1, Job j2, int M, int N, int K)
{
    extern __shared__ char smem[];
    const Job jb = (blockIdx.z == 0) ? j0 : (blockIdx.z == 1) ? j1 : j2;

    const uint32_t sbase = smem_to_u32(smem);
    const int tid = threadIdx.x;
    const int wid = tid >> 5, lane = tid & 31;
    const int bm = blockIdx.y * 128;
    const int bn = blockIdx.x * 128;
    const int wm = wid >> 2, wn = wid & 3;   // 2x4 warp grid, 64x32 tiles
    const int NCH = K / KC;

    const __half* Ab = jb.A + (size_t)bm * K;
    const __half* Wb = jb.W + (size_t)bn * K;

    auto load_chunk = [&](int kc, int s) {
        uint32_t st = sbase + s * STAGE_B;
        int koff = kc * KC;
        #pragma unroll
        for (int j = 0; j < 8; j++) {
            int q = tid + j * 256;
            int t = q >> 10;
            int r = (q >> 3) & 127;
            int seg = q & 7;
            const __half* src = (t ? Wb : Ab) + (size_t)r * K + koff + seg * 8;
            uint32_t dst = st + t * TILE_B + r * ROWB + seg * 16;
            asm volatile("cp.async.cg.shared.global [%0], [%1], 16;\n"
                         :: "r"(dst), "l"(src));
        }
        asm volatile("cp.async.commit_group;\n");
    };

    float acc[4][4][4];
    #pragma unroll
    for (int i = 0; i < 4; i++)
        #pragma unroll
        for (int j = 0; j < 4; j++)
            #pragma unroll
            for (int e = 0; e < 4; e++) acc[i][j][e] = 0.f;

    load_chunk(0, 0);
    load_chunk(1, 1);

    const uint32_t a_r = (lane & 15);
    const uint32_t a_k = (lane >> 4) * 16;
    const uint32_t b_r = (lane & 7) + ((lane >> 4) << 3);
    const uint32_t b_k = ((lane >> 3) & 1) * 16;

    for (int i = 0; i < NCH; i++) {
        int s = i % NSTAGE;
        if (i == NCH - 1)
            asm volatile("cp.async.wait_group 0;\n" ::: "memory");
        else
            asm volatile("cp.async.wait_group 1;\n" ::: "memory");
        __syncthreads();
        if (i + 2 < NCH) load_chunk(i + 2, (i + 2) % NSTAGE);

        uint32_t At = sbase + s * STAGE_B;
        uint32_t Wt = At + TILE_B;

        #pragma unroll
        for (int k16 = 0; k16 < 4; k16++) {
            uint32_t a[4][4];
            #pragma unroll
            for (int mi = 0; mi < 4; mi++) {
                uint32_t addr = At + (wm * 64 + mi * 16 + a_r) * ROWB
                              + k16 * 32 + a_k;
                ldsm_x4(a[mi][0], a[mi][1], a[mi][2], a[mi][3], addr);
            }
            uint32_t b[4][2];
            #pragma unroll
            for (int bp = 0; bp < 2; bp++) {
                uint32_t r0, r1, r2, r3;
                uint32_t addr = Wt + (wn * 32 + bp * 16 + b_r) * ROWB
                              + k16 * 32 + b_k;
                ldsm_x4(r0, r1, r2, r3, addr);
                b[2 * bp + 0][0] = r0; b[2 * bp + 0][1] = r1;
                b[2 * bp + 1][0] = r2; b[2 * bp + 1][1] = r3;
            }
            #pragma unroll
            for (int mi = 0; mi < 4; mi++)
                #pragma unroll
                for (int ni = 0; ni < 4; ni++)
                    mma16816(acc[mi][ni], a[mi], b[ni]);
        }
    }

    // epilogue
    const int r0 = bm + wm * 64 + (lane >> 2);
    const int c0 = bn + wn * 32 + (lane & 3) * 2;
    const int mode = jb.mode;
    #pragma unroll
    for (int mi = 0; mi < 4; mi++) {
        #pragma unroll
        for (int h = 0; h < 2; h++) {
            int row = r0 + mi * 16 + h * 8;
            #pragma unroll
            for (int ni = 0; ni < 4; ni++) {
                int col = c0 + ni * 8;
                size_t idx = (size_t)row * N + col;
                float2 bv = *(const float2*)(jb.bias + col);
                float v0 = acc[mi][ni][2 * h + 0] + bv.x;
                float v1 = acc[mi][ni][2 * h + 1] + bv.y;
                if (mode == 2) {
                    float2 rv = *(const float2*)(jb.resid + idx);
                    v0 += rv.x; v1 += rv.y;
                    float2 o; o.x = v0; o.y = v1;
                    *(float2*)(jb.outF + idx) = o;
                } else {
                    *(__half2*)(jb.outH + idx) = __floats2half2_rn(v0, v1);
                }
            }
        }
    }
}

// ===========================================================================
// base-phase cos/sin table
// ===========================================================================
__global__ void phase_table_kernel(const float* __restrict__ bp,
                                   float* __restrict__ cb,
                                   float* __restrict__ sb, int n) {
    int i = blockIdx.x * blockDim.x + threadIdx.x;
    if (i < n) {
        float s, c;
        sincosf(bp[i], &s, &c);
        cb[i] = c;
        sb[i] = s;
    }
}

// ===========================================================================
// Taylor sincos for tiny delta
// ===========================================================================
__device__ __forceinline__ void sincos_small(float x, float& s, float& c) {
    float x2 = x * x;
    s = x * fmaf(x2, fmaf(x2, fmaf(x2, -1.f / 5040.f, 1.f / 120.f), -1.f / 6.f), 1.f);
    c = fmaf(x2, fmaf(x2, fmaf(x2, -1.f / 720.f, 1.f / 24.f), -0.5f), 1.f);
}

// ===========================================================================
// Fused phasor bind + chunked cumsum + retrieval + LayerNorm -> fp16.
// Block = one (batch, chunk), 512 threads = one per feature d. Two barriers.
// ===========================================================================
#define CHK 64
#define NW  16

__global__ __launch_bounds__(512) void phasor_ln_kernel(
    const __half* __restrict__ V, const __half* __restrict__ KM,
    const __half* __restrict__ QM,
    const float* __restrict__ cb, const float* __restrict__ sbt,
    const float* __restrict__ msp,
    const float* __restrict__ lng, const float* __restrict__ lnb,
    __half* __restrict__ Oh, int S, int D)
{
    const int d = threadIdx.x;
    const int nC = S / CHK;
    const int b = blockIdx.x / nC;
    const int c = blockIdx.x % nC;

    const float ms  = msp[0];
    const float g   = lng[d];
    const float be  = lnb[d];
    const float inv = rsqrtf((float)D);

    const int lane = d & 31;
    const int w    = d >> 5;

    __shared__ float sm1[CHK * 17];
    __shared__ float sm2[CHK * 17];
    __shared__ float smu[CHK];
    __shared__ float srs[CHK];

    float r[CHK];
    float mr = 0.f, mi = 0.f;
    size_t base  = ((size_t)b * S + (size_t)c * CHK) * D + d;
    size_t pbase = ((size_t)c * CHK) * D + d;

    #pragma unroll
    for (int s = 0; s < CHK; s++) {
        size_t idx  = base + (size_t)s * D;
        size_t pidx = pbase + (size_t)s * D;

        float cbp = cb[pidx];
        float sbp = sbt[pidx];
        float dk = __half2float(KM[idx]) * ms;
        float dq = __half2float(QM[idx]) * ms;
        float sk, ck, sq, cq;
        sincos_small(dk, sk, ck);
        sincos_small(dq, sq, cq);

        float ckp = cbp * ck - sbp * sk;
        float skp = sbp * ck + cbp * sk;
        float cqp = cbp * cq - sbp * sq;
        float sqp = sbp * cq + cbp * sq;

        float v = __half2float(V[idx]);
        mr = fmaf(v, ckp, mr);
        mi = fmaf(v, skp, mi);

        float rv = (mr * cqp + mi * sqp) * inv;
        r[s] = rv;

        float s1 = rv, s2 = rv * rv;
        #pragma unroll
        for (int o = 16; o > 0; o >>= 1) {
            s1 += __shfl_xor_sync(0xffffffffu, s1, o);
            s2 += __shfl_xor_sync(0xffffffffu, s2, o);
        }
        if (lane == 0) { sm1[s * 17 + w] = s1; sm2[s * 17 + w] = s2; }
    }
    __syncthreads();

    if (d < CHK) {
        float a1 = 0.f, a2 = 0.f;
        #pragma unroll
        for (int j = 0; j < NW; j++) {
            a1 += sm1[d * 17 + j];
            a2 += sm2[d * 17 + j];
        }
        float mu = a1 / (float)D;
        smu[d] = mu;
        srs[d] = rsqrtf(a2 / (float)D - mu * mu + 1e-5f);
    }
    __syncthreads();

    #pragma unroll
    for (int s = 0; s < CHK; s++) {
        float normed = (r[s] - smu[s]) * srs[s] * g + be;
        Oh[base + (size_t)s * D] = __float2half(normed);
    }
}

// ===========================================================================
// Launch
// ===========================================================================
extern "C" void kernel_launch(void* const* d_in, const int* in_sizes, int n_in,
                              void* d_out, int out_size)
{
    const float* x    = (const float*)d_in[0];
    const float* bp   = (const float*)d_in[1];
    const float* Wk   = (const float*)d_in[2];
    const float* bk   = (const float*)d_in[3];
    const float* Wv   = (const float*)d_in[4];
    const float* bv   = (const float*)d_in[5];
    const float* Wq   = (const float*)d_in[6];
    const float* bq   = (const float*)d_in[7];
    const float* Wkm  = (const float*)d_in[8];
    const float* bkm  = (const float*)d_in[9];
    const float* Wqm  = (const float*)d_in[10];
    const float* bqm  = (const float*)d_in[11];
    const float* ms   = (const float*)d_in[12];
    const float* lng  = (const float*)d_in[13];
    const float* lnb  = (const float*)d_in[14];
    const float* Wo   = (const float*)d_in[15];
    const float* bo   = (const float*)d_in[16];
    float* out = (float*)d_out;

    const int D  = in_sizes[3];         // 512
    const int SD = in_sizes[1];         // S*D
    const int S  = SD / D;              // 4096
    const int M  = in_sizes[0] / D;     // 16384

    __half* hp = nullptr;   cudaGetSymbolAddress((void**)&hp, g_h);
    __half* whp = nullptr;  cudaGetSymbolAddress((void**)&whp, g_wh);
    float* cbuf = nullptr;  cudaGetSymbolAddress((void**)&cbuf, g_cb);
    float* sbuf = nullptr;  cudaGetSymbolAddress((void**)&sbuf, g_sb);
    float* bcp = nullptr;   cudaGetSymbolAddress((void**)&bcp, g_bc);
    float* zerop = nullptr; cudaGetSymbolAddress((void**)&zerop, g_zero);

    __half* xh  = hp + 0L * MAXELEM;
    __half* NBh = hp + 1L * MAXELEM;
    __half* KMh = hp + 2L * MAXELEM;
    __half* QMh = hp + 3L * MAXELEM;
    __half* Vh  = hp + 4L * MAXELEM;

    __half* Wh[6];
    for (int j = 0; j < 6; j++) Wh[j] = whp + (size_t)j * WELEM;
    __half* WkT  = whp + 6L * WELEM;
    __half* WqT  = whp + 7L * WELEM;
    __half* Wckm = whp + 8L * WELEM;
    __half* Wcqm = whp + 9L * WELEM;

    float* bckm = bcp;
    float* bcqm = bcp + 512;

    cudaFuncSetAttribute(gemm_h, cudaFuncAttributeMaxDynamicSharedMemorySize,
                         GEMM_SMEM);

    // ---- launch 0: all fp32->fp16 conversions ----
    CvtArgs ca;
    ca.x = (const float4*)x;
    ca.w[0] = (const float4*)Wk;  ca.w[1] = (const float4*)Wv;
    ca.w[2] = (const float4*)Wq;  ca.w[3] = (const float4*)Wkm;
    ca.w[4] = (const float4*)Wqm; ca.w[5] = (const float4*)Wo;
    ca.xh = (__half2*)xh;
    for (int j = 0; j < 6; j++) ca.wh[j] = (__half2*)Wh[j];
    ca.x4 = M * D / 4;
    ca.w4 = WELEM / 4;
    int totblk = (ca.x4 + 6 * ca.w4 + 255) / 256;
    tohalf_all<<<totblk, 256>>>(ca);

    // ---- launch 1: transposes + composite biases ----
    prep_kernel<<<640, 256>>>(Wh[0], Wh[2], WkT, WqT, Wkm, Wqm,
                              bk, bq, bkm, bqm, bckm, bcqm);

    // ---- launch 2: composite weights Wc = Wm @ W  (2 small jobs) ----
    Job jCk = { Wh[3], WkT, zerop, nullptr, nullptr, Wckm, 1 };
    Job jCq = { Wh[4], WqT, zerop, nullptr, nullptr, Wcqm, 1 };
    dim3 gc(D / 128, D / 128, 2);
    gemm_h<<<gc, 256, GEMM_SMEM>>>(jCk, jCq, jCq, D, D, D);

    // ---- launch 3: BIG fused GEMM — V, KM, QM from x (profiled slot) ----
    Job jV  = { xh, Wh[1], bv,   nullptr, nullptr, Vh,  1 };
    Job jKM = { xh, Wckm,  bckm, nullptr, nullptr, KMh, 1 };
    Job jQM = { xh, Wcqm,  bcqm, nullptr, nullptr, QMh, 1 };
    dim3 g3(D / 128, M / 128, 3);
    gemm_h<<<g3, 256, GEMM_SMEM>>>(jV, jKM, jQM, M, D, D);

    // ---- launch 4: phase table ----
    phase_table_kernel<<<(SD + 255) / 256, 256>>>(bp, cbuf, sbuf, SD);

    // ---- launch 5: phasor + cumsum + retrieval + LayerNorm ----
    phasor_ln_kernel<<<(M / CHK), D>>>(Vh, KMh, QMh, cbuf, sbuf, ms, lng, lnb,
                                       NBh, S, D);

    // ---- launch 6: out = x + normed@Wo^T + bo ----
    Job jO = { NBh, Wh[5], bo, x, out, nullptr, 2 };
    dim3 g1(D / 128, M / 128, 1);
    gemm_h<<<g1, 256, GEMM_SMEM>>>(jO, jO, jO, M, D, D);
}

// round 8
// speedup vs baseline: 1.5275x; 1.1513x over previous
#include <cuda_runtime.h>
#include <cuda_fp16.h>
#include <math.h>
#include <stdint.h>

// ===========================================================================
// Scratch (device globals; no allocation allowed)
// B=4, S=4096, D=512 -> M = 16384
// ===========================================================================
#define MAXELEM (16384 * 512)
#define MAXPH   (4096 * 512)
#define WELEM   (512 * 512)

__device__ __align__(256) __half g_h[5][MAXELEM];    // xh, NBh, KMh, QMh, Vh
__device__ __align__(256) __half g_wh[10][WELEM];    // Wk..Wo, WkT, WqT, Wc_km, Wc_qm
__device__ __align__(256) __half2 g_cs[MAXPH];       // packed (cos, sin) of base phase
__device__ float g_bc[2][512];                       // composite biases
__device__ float g_zero[512];                        // stays zero (.bss)

// ===========================================================================
// helpers
// ===========================================================================
__device__ __forceinline__ uint32_t smem_to_u32(const void* smem_ptr) {
    uint32_t addr;
    asm("{ .reg .u64 tmp; cvta.to.shared.u64 tmp, %1; cvt.u32.u64 %0, tmp; }"
        : "=r"(addr) : "l"(smem_ptr));
    return addr;
}

__device__ __forceinline__ void ldsm_x4(uint32_t& r0, uint32_t& r1,
                                        uint32_t& r2, uint32_t& r3, uint32_t a) {
    asm volatile("ldmatrix.sync.aligned.m8n8.x4.shared.b16 {%0,%1,%2,%3}, [%4];\n"
                 : "=r"(r0), "=r"(r1), "=r"(r2), "=r"(r3) : "r"(a));
}

__device__ __forceinline__ void mma16816(float* c, const uint32_t* a,
                                         const uint32_t* b) {
    asm volatile(
        "mma.sync.aligned.m16n8k16.row.col.f32.f16.f16.f32 "
        "{%0,%1,%2,%3},{%4,%5,%6,%7},{%8,%9},{%0,%1,%2,%3};\n"
        : "+f"(c[0]), "+f"(c[1]), "+f"(c[2]), "+f"(c[3])
        : "r"(a[0]), "r"(a[1]), "r"(a[2]), "r"(a[3]), "r"(b[0]), "r"(b[1]));
}

__device__ __forceinline__ void mma16816h(uint32_t* c, const uint32_t* a,
                                          const uint32_t* b) {
    asm volatile(
        "mma.sync.aligned.m16n8k16.row.col.f16.f16.f16.f16 "
        "{%0,%1},{%2,%3,%4,%5},{%6,%7},{%0,%1};\n"
        : "+r"(c[0]), "+r"(c[1])
        : "r"(a[0]), "r"(a[1]), "r"(a[2]), "r"(a[3]), "r"(b[0]), "r"(b[1]));
}

// ===========================================================================
// Launch 0: mega elementwise kernel — fuses:
//   [0, bx)        x fp32->fp16 (float4 granules)
//   [bx, bw)       6 weights fp32->fp16
//   [bw, bt)       packed cos/sin phase table (fp16)
//   [bt, btr)      transpose Wk, Wq (fp32 src -> fp16 transposed)
//   [btr, bbi)     composite biases bc = Wm @ b1 + b2
// ===========================================================================
struct MegaArgs {
    const float4* x;
    const float4* w[6];
    __half2* xh;
    __half2* wh[6];
    const float* bp;       // base phases
    __half2* cs;           // packed table
    const float* WkF; const float* WqF;   // fp32 weight sources for transpose
    __half* WkT; __half* WqT;
    const float* Wkm; const float* Wqm;
    const float* bk; const float* bq;
    const float* bkm; const float* bqm;
    float* bckm; float* bcqm;
    int x4, w4, n_tab;
    int bx, bw, bt, btr;
};

__global__ void mega_kernel(MegaArgs a) {
    int blk = blockIdx.x;
    int tid = threadIdx.x;
    if (blk < a.bx) {                                // x convert
        int j = blk * 256 + tid;
        float4 v = a.x[j];
        a.xh[2 * j + 0] = __floats2half2_rn(v.x, v.y);
        a.xh[2 * j + 1] = __floats2half2_rn(v.z, v.w);
    } else if (blk < a.bw) {                         // weight convert
        int q = (blk - a.bx) * 256 + tid;
        int t = q / a.w4;
        int j = q - t * a.w4;
        float4 v = a.w[t][j];
        a.wh[t][2 * j + 0] = __floats2half2_rn(v.x, v.y);
        a.wh[t][2 * j + 1] = __floats2half2_rn(v.z, v.w);
    } else if (blk < a.bt) {                         // phase table
        int j = (blk - a.bw) * 256 + tid;
        float s, c;
        sincosf(a.bp[j], &s, &c);
        a.cs[j] = __floats2half2_rn(c, s);
    } else if (blk < a.btr) {                        // transpose Wk / Wq
        __shared__ float sm[32][33];
        int idx = blk - a.bt;                        // 0..511
        const float* src = (idx < 256) ? a.WkF : a.WqF;
        __half* dst = (idx < 256) ? a.WkT : a.WqT;
        idx &= 255;
        int tr = idx >> 4, tc = idx & 15;
        int tx = tid & 31, ty = tid >> 5;            // 32 x 8
        #pragma unroll
        for (int i = 0; i < 4; i++)
            sm[ty + i * 8][tx] = src[(tr * 32 + ty + i * 8) * 512 + tc * 32 + tx];
        __syncthreads();
        #pragma unroll
        for (int i = 0; i < 4; i++)
            dst[(tc * 32 + ty + i * 8) * 512 + tr * 32 + tx] =
                __float2half(sm[tx][ty + i * 8]);
    } else {                                         // composite biases
        int idx = blk - a.btr;                       // 0..127
        int isQ = (idx >= 64);
        const float* Wm = isQ ? a.Wqm : a.Wkm;
        const float* b1 = isQ ? a.bq  : a.bk;
        const float* b2 = isQ ? a.bqm : a.bkm;
        float* bc = isQ ? a.bcqm : a.bckm;
        int row = (idx & 63) * 8 + (tid >> 5);
        int lane = tid & 31;
        float s = 0.f;
        #pragma unroll
        for (int j = 0; j < 16; j++)
            s += Wm[row * 512 + lane + 32 * j] * b1[lane + 32 * j];
        #pragma unroll
        for (int o = 16; o > 0; o >>= 1)
            s += __shfl_xor_sync(0xffffffffu, s, o);
        if (lane == 0) bc[row] = s + b2[row];
    }
}

// ===========================================================================
// Shared GEMM config
// ===========================================================================
#define KC 64
#define ROWB 144
#define TILE_B (128 * ROWB)
#define STAGE_B (2 * TILE_B)            // 36864

struct Job {
    const __half* A;
    const __half* W;
    const float*  bias;
    const float*  resid;
    float*        outF;
    __half*       outH;
    int           mode;
};

// ===========================================================================
// fp32-accumulate HMMA GEMM (V, out, composite). 256 thr, 2 CTAs/SM,
// 3-stage ring. mode 1: fp16 out; mode 2: fp32 out + resid.
// ===========================================================================
#define NSTAGE3 3
#define GEMM_SMEM_F32 (NSTAGE3 * STAGE_B)   // 110592

__global__ __launch_bounds__(256, 2) void gemm_h(
    Job j0, Job j1, Job j2, int M, int N, int K)
{
    extern __shared__ char smem[];
    const Job jb = (blockIdx.z == 0) ? j0 : (blockIdx.z == 1) ? j1 : j2;

    const uint32_t sbase = smem_to_u32(smem);
    const int tid = threadIdx.x;
    const int wid = tid >> 5, lane = tid & 31;
    const int bm = blockIdx.y * 128;
    const int bn = blockIdx.x * 128;
    const int wm = wid >> 2, wn = wid & 3;
    const int NCH = K / KC;

    const __half* Ab = jb.A + (size_t)bm * K;
    const __half* Wb = jb.W + (size_t)bn * K;

    auto load_chunk = [&](int kc, int s) {
        uint32_t st = sbase + s * STAGE_B;
        int koff = kc * KC;
        #pragma unroll
        for (int j = 0; j < 8; j++) {
            int q = tid + j * 256;
            int t = q >> 10;
            int r = (q >> 3) & 127;
            int seg = q & 7;
            const __half* src = (t ? Wb : Ab) + (size_t)r * K + koff + seg * 8;
            uint32_t dst = st + t * TILE_B + r * ROWB + seg * 16;
            asm volatile("cp.async.cg.shared.global [%0], [%1], 16;\n"
                         :: "r"(dst), "l"(src));
        }
        asm volatile("cp.async.commit_group;\n");
    };

    float acc[4][4][4];
    #pragma unroll
    for (int i = 0; i < 4; i++)
        #pragma unroll
        for (int j = 0; j < 4; j++)
            #pragma unroll
            for (int e = 0; e < 4; e++) acc[i][j][e] = 0.f;

    load_chunk(0, 0);
    load_chunk(1, 1);

    const uint32_t a_r = (lane & 15);
    const uint32_t a_k = (lane >> 4) * 16;
    const uint32_t b_r = (lane & 7) + ((lane >> 4) << 3);
    const uint32_t b_k = ((lane >> 3) & 1) * 16;

    for (int i = 0; i < NCH; i++) {
        int s = i % NSTAGE3;
        if (i == NCH - 1)
            asm volatile("cp.async.wait_group 0;\n" ::: "memory");
        else
            asm volatile("cp.async.wait_group 1;\n" ::: "memory");
        __syncthreads();
        if (i + 2 < NCH) load_chunk(i + 2, (i + 2) % NSTAGE3);

        uint32_t At = sbase + s * STAGE_B;
        uint32_t Wt = At + TILE_B;

        #pragma unroll
        for (int k16 = 0; k16 < 4; k16++) {
            uint32_t a[4][4];
            #pragma unroll
            for (int mi = 0; mi < 4; mi++) {
                uint32_t addr = At + (wm * 64 + mi * 16 + a_r) * ROWB
                              + k16 * 32 + a_k;
                ldsm_x4(a[mi][0], a[mi][1], a[mi][2], a[mi][3], addr);
            }
            uint32_t b[4][2];
            #pragma unroll
            for (int bp = 0; bp < 2; bp++) {
                uint32_t r0, r1, r2, r3;
                uint32_t addr = Wt + (wn * 32 + bp * 16 + b_r) * ROWB
                              + k16 * 32 + b_k;
                ldsm_x4(r0, r1, r2, r3, addr);
                b[2 * bp + 0][0] = r0; b[2 * bp + 0][1] = r1;
                b[2 * bp + 1][0] = r2; b[2 * bp + 1][1] = r3;
            }
            #pragma unroll
            for (int mi = 0; mi < 4; mi++)
                #pragma unroll
                for (int ni = 0; ni < 4; ni++)
                    mma16816(acc[mi][ni], a[mi], b[ni]);
        }
    }

    // epilogue (bias hoisted)
    const int r0 = bm + wm * 64 + (lane >> 2);
    const int c0 = bn + wn * 32 + (lane & 3) * 2;
    const int mode = jb.mode;
    float2 bv[4];
    #pragma unroll
    for (int ni = 0; ni < 4; ni++)
        bv[ni] = *(const float2*)(jb.bias + c0 + ni * 8);
    #pragma unroll
    for (int mi = 0; mi < 4; mi++) {
        #pragma unroll
        for (int h = 0; h < 2; h++) {
            int row = r0 + mi * 16 + h * 8;
            #pragma unroll
            for (int ni = 0; ni < 4; ni++) {
                int col = c0 + ni * 8;
                size_t idx = (size_t)row * N + col;
                float v0 = acc[mi][ni][2 * h + 0] + bv[ni].x;
                float v1 = acc[mi][ni][2 * h + 1] + bv[ni].y;
                if (mode == 2) {
                    float2 rv = *(const float2*)(jb.resid + idx);
                    v0 += rv.x; v1 += rv.y;
                    float2 o; o.x = v0; o.y = v1;
                    *(float2*)(jb.outF + idx) = o;
                } else {
                    *(__half2*)(jb.outH + idx) = __floats2half2_rn(v0, v1);
                }
            }
        }
    }
}

// ===========================================================================
// fp16-accumulate HMMA GEMM (KM/QM phase deltas). 256 thr, targets
// 3 CTAs/SM (<=84 regs), 2-stage ring with distance-1 prefetch.
// Always mode-1 (fp16 out + fp32 bias).
// ===========================================================================
#define GEMM_SMEM_F16 (2 * STAGE_B)     // 73728

__global__ __launch_bounds__(256, 3) void gemm_h16(
    Job j0, Job j1, int M, int N, int K)
{
    extern __shared__ char smem[];
    const Job jb = (blockIdx.z == 0) ? j0 : j1;

    const uint32_t sbase = smem_to_u32(smem);
    const int tid = threadIdx.x;
    const int wid = tid >> 5, lane = tid & 31;
    const int bm = blockIdx.y * 128;
    const int bn = blockIdx.x * 128;
    const int wm = wid >> 2, wn = wid & 3;
    const int NCH = K / KC;

    const __half* Ab = jb.A + (size_t)bm * K;
    const __half* Wb = jb.W + (size_t)bn * K;

    auto load_chunk = [&](int kc, int s) {
        uint32_t st = sbase + s * STAGE_B;
        int koff = kc * KC;
        #pragma unroll
        for (int j = 0; j < 8; j++) {
            int q = tid + j * 256;
            int t = q >> 10;
            int r = (q >> 3) & 127;
            int seg = q & 7;
            const __half* src = (t ? Wb : Ab) + (size_t)r * K + koff + seg * 8;
            uint32_t dst = st + t * TILE_B + r * ROWB + seg * 16;
            asm volatile("cp.async.cg.shared.global [%0], [%1], 16;\n"
                         :: "r"(dst), "l"(src));
        }
        asm volatile("cp.async.commit_group;\n");
    };

    uint32_t acc[4][4][2];
    #pragma unroll
    for (int i = 0; i < 4; i++)
        #pragma unroll
        for (int j = 0; j < 4; j++) { acc[i][j][0] = 0u; acc[i][j][1] = 0u; }

    load_chunk(0, 0);

    const uint32_t a_r = (lane & 15);
    const uint32_t a_k = (lane >> 4) * 16;
    const uint32_t b_r = (lane & 7) + ((lane >> 4) << 3);
    const uint32_t b_k = ((lane >> 3) & 1) * 16;

    for (int i = 0; i < NCH; i++) {
        int s = i & 1;
        __syncthreads();                       // all warps done with stage 1-s
        if (i + 1 < NCH) {
            load_chunk(i + 1, 1 - s);
            asm volatile("cp.async.wait_group 1;\n" ::: "memory");  // chunk i done
        } else {
            asm volatile("cp.async.wait_group 0;\n" ::: "memory");
        }
        __syncthreads();                       // stage s visible to all

        uint32_t At = sbase + s * STAGE_B;
        uint32_t Wt = At + TILE_B;

        #pragma unroll
        for (int k16 = 0; k16 < 4; k16++) {
            uint32_t a[4][4];
            #pragma unroll
            for (int mi = 0; mi < 4; mi++) {
                uint32_t addr = At + (wm * 64 + mi * 16 + a_r) * ROWB
                              + k16 * 32 + a_k;
                ldsm_x4(a[mi][0], a[mi][1], a[mi][2], a[mi][3], addr);
            }
            uint32_t b[4][2];
            #pragma unroll
            for (int bp = 0; bp < 2; bp++) {
                uint32_t r0, r1, r2, r3;
                uint32_t addr = Wt + (wn * 32 + bp * 16 + b_r) * ROWB
                              + k16 * 32 + b_k;
                ldsm_x4(r0, r1, r2, r3, addr);
                b[2 * bp + 0][0] = r0; b[2 * bp + 0][1] = r1;
                b[2 * bp + 1][0] = r2; b[2 * bp + 1][1] = r3;
            }
            #pragma unroll
            for (int mi = 0; mi < 4; mi++)
                #pragma unroll
                for (int ni = 0; ni < 4; ni++)
                    mma16816h(acc[mi][ni], a[mi], b[ni]);
        }
    }

    // epilogue
    const int r0 = bm + wm * 64 + (lane >> 2);
    const int c0 = bn + wn * 32 + (lane & 3) * 2;
    float2 bv[4];
    #pragma unroll
    for (int ni = 0; ni < 4; ni++)
        bv[ni] = *(const float2*)(jb.bias + c0 + ni * 8);
    #pragma unroll
    for (int mi = 0; mi < 4; mi++) {
        #pragma unroll
        for (int h = 0; h < 2; h++) {
            int row = r0 + mi * 16 + h * 8;
            #pragma unroll
            for (int ni = 0; ni < 4; ni++) {
                int col = c0 + ni * 8;
                size_t idx = (size_t)row * N + col;
                float2 p = __half22float2(
                    *reinterpret_cast<__half2*>(&acc[mi][ni][h]));
                *(__half2*)(jb.outH + idx) =
                    __floats2half2_rn(p.x + bv[ni].x, p.y + bv[ni].y);
            }
        }
    }
}

// ===========================================================================
// Taylor sincos for tiny delta
// ===========================================================================
__device__ __forceinline__ void sincos_small(float x, float& s, float& c) {
    float x2 = x * x;
    s = x * fmaf(x2, fmaf(x2, fmaf(x2, -1.f / 5040.f, 1.f / 120.f), -1.f / 6.f), 1.f);
    c = fmaf(x2, fmaf(x2, fmaf(x2, -1.f / 720.f, 1.f / 24.f), -0.5f), 1.f);
}

// ===========================================================================
// Fused phasor bind + chunked cumsum + retrieval + LayerNorm -> fp16.
// Block = one (batch, chunk), 512 threads = one per feature d. Two barriers.
// ===========================================================================
#define CHK 64
#define NW  16

__global__ __launch_bounds__(512) void phasor_ln_kernel(
    const __half* __restrict__ V, const __half* __restrict__ KM,
    const __half* __restrict__ QM,
    const __half2* __restrict__ cs,
    const float* __restrict__ msp,
    const float* __restrict__ lng, const float* __restrict__ lnb,
    __half* __restrict__ Oh, int S, int D)
{
    const int d = threadIdx.x;
    const int nC = S / CHK;
    const int b = blockIdx.x / nC;
    const int c = blockIdx.x % nC;

    const float ms  = msp[0];
    const float g   = lng[d];
    const float be  = lnb[d];
    const float inv = rsqrtf((float)D);

    const int lane = d & 31;
    const int w    = d >> 5;

    __shared__ float sm1[CHK * 17];
    __shared__ float sm2[CHK * 17];
    __shared__ float smu[CHK];
    __shared__ float srs[CHK];

    float r[CHK];
    float mr = 0.f, mi = 0.f;
    size_t base  = ((size_t)b * S + (size_t)c * CHK) * D + d;
    size_t pbase = ((size_t)c * CHK) * D + d;

    #pragma unroll
    for (int s = 0; s < CHK; s++) {
        size_t idx  = base + (size_t)s * D;
        size_t pidx = pbase + (size_t)s * D;

        float2 cssb = __half22float2(cs[pidx]);
        float cbp = cssb.x;
        float sbp = cssb.y;
        float dk = __half2float(KM[idx]) * ms;
        float dq = __half2float(QM[idx]) * ms;
        float sk, ck, sq, cq;
        sincos_small(dk, sk, ck);
        sincos_small(dq, sq, cq);

        float ckp = cbp * ck - sbp * sk;
        float skp = sbp * ck + cbp * sk;
        float cqp = cbp * cq - sbp * sq;
        float sqp = sbp * cq + cbp * sq;

        float v = __half2float(V[idx]);
        mr = fmaf(v, ckp, mr);
        mi = fmaf(v, skp, mi);

        float rv = (mr * cqp + mi * sqp) * inv;
        r[s] = rv;

        float s1 = rv, s2 = rv * rv;
        #pragma unroll
        for (int o = 16; o > 0; o >>= 1) {
            s1 += __shfl_xor_sync(0xffffffffu, s1, o);
            s2 += __shfl_xor_sync(0xffffffffu, s2, o);
        }
        if (lane == 0) { sm1[s * 17 + w] = s1; sm2[s * 17 + w] = s2; }
    }
    __syncthreads();

    if (d < CHK) {
        float a1 = 0.f, a2 = 0.f;
        #pragma unroll
        for (int j = 0; j < NW; j++) {
            a1 += sm1[d * 17 + j];
            a2 += sm2[d * 17 + j];
        }
        float mu = a1 / (float)D;
        smu[d] = mu;
        srs[d] = rsqrtf(a2 / (float)D - mu * mu + 1e-5f);
    }
    __syncthreads();

    #pragma unroll
    for (int s = 0; s < CHK; s++) {
        float normed = (r[s] - smu[s]) * srs[s] * g + be;
        Oh[base + (size_t)s * D] = __float2half(normed);
    }
}

// ===========================================================================
// Launch
// ===========================================================================
extern "C" void kernel_launch(void* const* d_in, const int* in_sizes, int n_in,
                              void* d_out, int out_size)
{
    const float* x    = (const float*)d_in[0];
    const float* bp   = (const float*)d_in[1];
    const float* Wk   = (const float*)d_in[2];
    const float* bk   = (const float*)d_in[3];
    const float* Wv   = (const float*)d_in[4];
    const float* bv   = (const float*)d_in[5];
    const float* Wq   = (const float*)d_in[6];
    const float* bq   = (const float*)d_in[7];
    const float* Wkm  = (const float*)d_in[8];
    const float* bkm  = (const float*)d_in[9];
    const float* Wqm  = (const float*)d_in[10];
    const float* bqm  = (const float*)d_in[11];
    const float* ms   = (const float*)d_in[12];
    const float* lng  = (const float*)d_in[13];
    const float* lnb  = (const float*)d_in[14];
    const float* Wo   = (const float*)d_in[15];
    const float* bo   = (const float*)d_in[16];
    float* out = (float*)d_out;

    const int D  = in_sizes[3];         // 512
    const int SD = in_sizes[1];         // S*D
    const int S  = SD / D;              // 4096
    const int M  = in_sizes[0] / D;     // 16384

    __half* hp = nullptr;    cudaGetSymbolAddress((void**)&hp, g_h);
    __half* whp = nullptr;   cudaGetSymbolAddress((void**)&whp, g_wh);
    __half2* csb = nullptr;  cudaGetSymbolAddress((void**)&csb, g_cs);
    float* bcp = nullptr;    cudaGetSymbolAddress((void**)&bcp, g_bc);
    float* zerop = nullptr;  cudaGetSymbolAddress((void**)&zerop, g_zero);

    __half* xh  = hp + 0L * MAXELEM;
    __half* NBh = hp + 1L * MAXELEM;
    __half* KMh = hp + 2L * MAXELEM;
    __half* QMh = hp + 3L * MAXELEM;
    __half* Vh  = hp + 4L * MAXELEM;

    __half* Wh[6];
    for (int j = 0; j < 6; j++) Wh[j] = whp + (size_t)j * WELEM;
    __half* WkT  = whp + 6L * WELEM;
    __half* WqT  = whp + 7L * WELEM;
    __half* Wckm = whp + 8L * WELEM;
    __half* Wcqm = whp + 9L * WELEM;

    float* bckm = bcp;
    float* bcqm = bcp + 512;

    cudaFuncSetAttribute(gemm_h, cudaFuncAttributeMaxDynamicSharedMemorySize,
                         GEMM_SMEM_F32);
    cudaFuncSetAttribute(gemm_h16, cudaFuncAttributeMaxDynamicSharedMemorySize,
                         GEMM_SMEM_F16);

    // ---- launch 0: mega elementwise (cvt + table + transpose + biases) ----
    MegaArgs ma;
    ma.x = (const float4*)x;
    ma.w[0] = (const float4*)Wk;  ma.w[1] = (const float4*)Wv;
    ma.w[2] = (const float4*)Wq;  ma.w[3] = (const float4*)Wkm;
    ma.w[4] = (const float4*)Wqm; ma.w[5] = (const float4*)Wo;
    ma.xh = (__half2*)xh;
    for (int j = 0; j < 6; j++) ma.wh[j] = (__half2*)Wh[j];
    ma.bp = bp;  ma.cs = csb;
    ma.WkF = Wk; ma.WqF = Wq;
    ma.WkT = WkT; ma.WqT = WqT;
    ma.Wkm = Wkm; ma.Wqm = Wqm;
    ma.bk = bk; ma.bq = bq; ma.bkm = bkm; ma.bqm = bqm;
    ma.bckm = bckm; ma.bcqm = bcqm;
    ma.x4 = M * D / 4;
    ma.w4 = WELEM / 4;
    ma.n_tab = SD;
    ma.bx  = ma.x4 / 256;                   // 2048
    ma.bw  = ma.bx + 6 * (ma.w4 / 256);     // +1536
    ma.bt  = ma.bw + SD / 256;              // +8192
    ma.btr = ma.bt + 512;                   // transpose blocks
    int megablocks = ma.btr + 128;
    mega_kernel<<<megablocks, 256>>>(ma);

    // ---- launch 1: composite weights Wc = Wm @ W^T (2 small f32 jobs) ----
    Job jCk = { Wh[3], WkT, zerop, nullptr, nullptr, Wckm, 1 };
    Job jCq = { Wh[4], WqT, zerop, nullptr, nullptr, Wcqm, 1 };
    dim3 gc(D / 128, D / 128, 2);
    gemm_h<<<gc, 256, GEMM_SMEM_F32>>>(jCk, jCq, jCq, D, D, D);

    // ---- launch 2: V = x@Wv^T + bv (f32 acc) ----
    Job jV = { xh, Wh[1], bv, nullptr, nullptr, Vh, 1 };
    dim3 g1(D / 128, M / 128, 1);
    gemm_h<<<g1, 256, GEMM_SMEM_F32>>>(jV, jV, jV, M, D, D);

    // ---- launch 3: KM, QM (fp16 acc, 3 CTAs/SM)  [profiled slot] ----
    Job jKM = { xh, Wckm, bckm, nullptr, nullptr, KMh, 1 };
    Job jQM = { xh, Wcqm, bcqm, nullptr, nullptr, QMh, 1 };
    dim3 g2(D / 128, M / 128, 2);
    gemm_h16<<<g2, 256, GEMM_SMEM_F16>>>(jKM, jQM, M, D, D);

    // ---- launch 4: phasor + cumsum + retrieval + LayerNorm ----
    phasor_ln_kernel<<<(M / CHK), D>>>(Vh, KMh, QMh, csb, ms, lng, lnb,
                                       NBh, S, D);

    // ---- launch 5: out = x + normed@Wo^T + bo ----
    Job jO = { NBh, Wh[5], bo, x, out, nullptr, 2 };
    gemm_h<<<g1, 256, GEMM_SMEM_F32>>>(jO, jO, jO, M, D, D);
}

// round 9
// speedup vs baseline: 1.5945x; 1.0439x over previous
#include <cuda_runtime.h>
#include <cuda_fp16.h>
#include <math.h>
#include <stdint.h>

// ===========================================================================
// Scratch (device globals; no allocation allowed)
// B=4, S=4096, D=512 -> M = 16384
// ===========================================================================
#define MAXELEM (16384 * 512)
#define MAXPH   (4096 * 512)
#define WELEM   (512 * 512)

__device__ __align__(256) __half g_h[3][MAXELEM];     // xh, NBh, Vh
__device__ __align__(256) __half g_kq[2 * MAXELEM];   // KQ: [M, 1024]
__device__ __align__(256) __half g_wh[10][WELEM];     // Wk..Wo, WkT, WqT, Wckq(2)
__device__ __align__(256) __half2 g_cs[MAXPH];        // packed (cos,sin) base phase
__device__ float g_bc[1024];                          // combined composite bias
__device__ float g_zero[512];                         // stays zero (.bss)

// ===========================================================================
// helpers
// ===========================================================================
__device__ __forceinline__ uint32_t smem_to_u32(const void* smem_ptr) {
    uint32_t addr;
    asm("{ .reg .u64 tmp; cvta.to.shared.u64 tmp, %1; cvt.u32.u64 %0, tmp; }"
        : "=r"(addr) : "l"(smem_ptr));
    return addr;
}

__device__ __forceinline__ void ldsm_x4(uint32_t& r0, uint32_t& r1,
                                        uint32_t& r2, uint32_t& r3, uint32_t a) {
    asm volatile("ldmatrix.sync.aligned.m8n8.x4.shared.b16 {%0,%1,%2,%3}, [%4];\n"
                 : "=r"(r0), "=r"(r1), "=r"(r2), "=r"(r3) : "r"(a));
}

__device__ __forceinline__ void mma16816(float* c, const uint32_t* a,
                                         const uint32_t* b) {
    asm volatile(
        "mma.sync.aligned.m16n8k16.row.col.f32.f16.f16.f32 "
        "{%0,%1,%2,%3},{%4,%5,%6,%7},{%8,%9},{%0,%1,%2,%3};\n"
        : "+f"(c[0]), "+f"(c[1]), "+f"(c[2]), "+f"(c[3])
        : "r"(a[0]), "r"(a[1]), "r"(a[2]), "r"(a[3]), "r"(b[0]), "r"(b[1]));
}

__device__ __forceinline__ void mma16816h(uint32_t* c, const uint32_t* a,
                                          const uint32_t* b) {
    asm volatile(
        "mma.sync.aligned.m16n8k16.row.col.f16.f16.f16.f16 "
        "{%0,%1},{%2,%3,%4,%5},{%6,%7},{%0,%1};\n"
        : "+r"(c[0]), "+r"(c[1])
        : "r"(a[0]), "r"(a[1]), "r"(a[2]), "r"(a[3]), "r"(b[0]), "r"(b[1]));
}

// ===========================================================================
// Launch 0: mega elementwise kernel (cvt x + weights, phase table,
// transposes, composite biases)
// ===========================================================================
struct MegaArgs {
    const float4* x;
    const float4* w[6];
    __half2* xh;
    __half2* wh[6];
    const float* bp;
    __half2* cs;
    const float* WkF; const float* WqF;
    __half* WkT; __half* WqT;
    const float* Wkm; const float* Wqm;
    const float* bk; const float* bq;
    const float* bkm; const float* bqm;
    float* bckq;                 // [1024]: km 0-511, qm 512-1023
    int x4, w4;
    int bx, bw, bt, btr;
};

__global__ void mega_kernel(MegaArgs a) {
    int blk = blockIdx.x;
    int tid = threadIdx.x;
    if (blk < a.bx) {
        int j = blk * 256 + tid;
        float4 v = a.x[j];
        a.xh[2 * j + 0] = __floats2half2_rn(v.x, v.y);
        a.xh[2 * j + 1] = __floats2half2_rn(v.z, v.w);
    } else if (blk < a.bw) {
        int q = (blk - a.bx) * 256 + tid;
        int t = q / a.w4;
        int j = q - t * a.w4;
        float4 v = a.w[t][j];
        a.wh[t][2 * j + 0] = __floats2half2_rn(v.x, v.y);
        a.wh[t][2 * j + 1] = __floats2half2_rn(v.z, v.w);
    } else if (blk < a.bt) {
        int j = (blk - a.bw) * 256 + tid;
        float s, c;
        sincosf(a.bp[j], &s, &c);
        a.cs[j] = __floats2half2_rn(c, s);
    } else if (blk < a.btr) {
        __shared__ float sm[32][33];
        int idx = blk - a.bt;
        const float* src = (idx < 256) ? a.WkF : a.WqF;
        __half* dst = (idx < 256) ? a.WkT : a.WqT;
        idx &= 255;
        int tr = idx >> 4, tc = idx & 15;
        int tx = tid & 31, ty = tid >> 5;
        #pragma unroll
        for (int i = 0; i < 4; i++)
            sm[ty + i * 8][tx] = src[(tr * 32 + ty + i * 8) * 512 + tc * 32 + tx];
        __syncthreads();
        #pragma unroll
        for (int i = 0; i < 4; i++)
            dst[(tc * 32 + ty + i * 8) * 512 + tr * 32 + tx] =
                __float2half(sm[tx][ty + i * 8]);
    } else {
        int idx = blk - a.btr;               // 0..127
        int isQ = (idx >= 64);
        const float* Wm = isQ ? a.Wqm : a.Wkm;
        const float* b1 = isQ ? a.bq  : a.bk;
        const float* b2 = isQ ? a.bqm : a.bkm;
        float* bc = a.bckq + (isQ ? 512 : 0);
        int row = (idx & 63) * 8 + (tid >> 5);
        int lane = tid & 31;
        float s = 0.f;
        #pragma unroll
        for (int j = 0; j < 16; j++)
            s += Wm[row * 512 + lane + 32 * j] * b1[lane + 32 * j];
        #pragma unroll
        for (int o = 16; o > 0; o >>= 1)
            s += __shfl_xor_sync(0xffffffffu, s, o);
        if (lane == 0) bc[row] = s + b2[row];
    }
}

// ===========================================================================
// GEMM common
// ===========================================================================
#define KC 64
#define ROWB 144
#define TILE_B (128 * ROWB)             // 18432

struct Job {
    const __half* A;
    const __half* W;
    const float*  bias;
    const float*  resid;
    float*        outF;
    __half*       outH;
    int           mode;
    int           Mj;      // rows of this job (bm >= Mj -> idle CTA)
};

// ===========================================================================
// fp32-accumulate GEMM (V, composite, out). 128x128 tile, 256 thr,
// 2 CTAs/SM, 3-stage ring. mode 1: fp16 out; mode 2: fp32 out + resid.
// ===========================================================================
#define STAGE_F32 (2 * TILE_B)              // 36864
#define GEMM_SMEM_F32 (3 * STAGE_F32)       // 110592

__global__ __launch_bounds__(256, 2) void gemm_h(
    Job j0, Job j1, Job j2, int N, int K)
{
    extern __shared__ char smem[];
    const Job jb = (blockIdx.z == 0) ? j0 : (blockIdx.z == 1) ? j1 : j2;

    const int bm = blockIdx.y * 128;
    if (bm >= jb.Mj) return;
    const int bn = blockIdx.x * 128;

    const uint32_t sbase = smem_to_u32(smem);
    const int tid = threadIdx.x;
    const int wid = tid >> 5, lane = tid & 31;
    const int wm = wid >> 2, wn = wid & 3;
    const int NCH = K / KC;

    const __half* Ab = jb.A + (size_t)bm * K;
    const __half* Wb = jb.W + (size_t)bn * K;

    auto load_chunk = [&](int kc, int s) {
        uint32_t st = sbase + s * STAGE_F32;
        int koff = kc * KC;
        #pragma unroll
        for (int j = 0; j < 8; j++) {
            int q = tid + j * 256;
            int t = q >> 10;
            int r = (q >> 3) & 127;
            int seg = q & 7;
            const __half* src = (t ? Wb : Ab) + (size_t)r * K + koff + seg * 8;
            uint32_t dst = st + t * TILE_B + r * ROWB + seg * 16;
            asm volatile("cp.async.cg.shared.global [%0], [%1], 16;\n"
                         :: "r"(dst), "l"(src));
        }
        asm volatile("cp.async.commit_group;\n");
    };

    float acc[4][4][4];
    #pragma unroll
    for (int i = 0; i < 4; i++)
        #pragma unroll
        for (int j = 0; j < 4; j++)
            #pragma unroll
            for (int e = 0; e < 4; e++) acc[i][j][e] = 0.f;

    load_chunk(0, 0);
    load_chunk(1, 1);

    const uint32_t a_r = (lane & 15);
    const uint32_t a_k = (lane >> 4) * 16;
    const uint32_t b_r = (lane & 7) + ((lane >> 4) << 3);
    const uint32_t b_k = ((lane >> 3) & 1) * 16;

    for (int i = 0; i < NCH; i++) {
        int s = i % 3;
        if (i == NCH - 1)
            asm volatile("cp.async.wait_group 0;\n" ::: "memory");
        else
            asm volatile("cp.async.wait_group 1;\n" ::: "memory");
        __syncthreads();
        if (i + 2 < NCH) load_chunk(i + 2, (i + 2) % 3);

        uint32_t At = sbase + s * STAGE_F32;
        uint32_t Wt = At + TILE_B;

        #pragma unroll
        for (int k16 = 0; k16 < 4; k16++) {
            uint32_t a[4][4];
            #pragma unroll
            for (int mi = 0; mi < 4; mi++) {
                uint32_t addr = At + (wm * 64 + mi * 16 + a_r) * ROWB
                              + k16 * 32 + a_k;
                ldsm_x4(a[mi][0], a[mi][1], a[mi][2], a[mi][3], addr);
            }
            uint32_t b[4][2];
            #pragma unroll
            for (int bp = 0; bp < 2; bp++) {
                uint32_t r0, r1, r2, r3;
                uint32_t addr = Wt + (wn * 32 + bp * 16 + b_r) * ROWB
                              + k16 * 32 + b_k;
                ldsm_x4(r0, r1, r2, r3, addr);
                b[2 * bp + 0][0] = r0; b[2 * bp + 0][1] = r1;
                b[2 * bp + 1][0] = r2; b[2 * bp + 1][1] = r3;
            }
            #pragma unroll
            for (int mi = 0; mi < 4; mi++)
                #pragma unroll
                for (int ni = 0; ni < 4; ni++)
                    mma16816(acc[mi][ni], a[mi], b[ni]);
        }
    }

    const int r0 = bm + wm * 64 + (lane >> 2);
    const int c0 = bn + wn * 32 + (lane & 3) * 2;
    const int mode = jb.mode;
    float2 bv[4];
    #pragma unroll
    for (int ni = 0; ni < 4; ni++)
        bv[ni] = *(const float2*)(jb.bias + c0 + ni * 8);
    #pragma unroll
    for (int mi = 0; mi < 4; mi++) {
        #pragma unroll
        for (int h = 0; h < 2; h++) {
            int row = r0 + mi * 16 + h * 8;
            #pragma unroll
            for (int ni = 0; ni < 4; ni++) {
                int col = c0 + ni * 8;
                size_t idx = (size_t)row * N + col;
                float v0 = acc[mi][ni][2 * h + 0] + bv[ni].x;
                float v1 = acc[mi][ni][2 * h + 1] + bv[ni].y;
                if (mode == 2) {
                    float2 rv = *(const float2*)(jb.resid + idx);
                    v0 += rv.x; v1 += rv.y;
                    float2 o; o.x = v0; o.y = v1;
                    *(float2*)(jb.outF + idx) = o;
                } else {
                    *(__half2*)(jb.outH + idx) = __floats2half2_rn(v0, v1);
                }
            }
        }
    }
}

// ===========================================================================
// fp16-accumulate GEMM for KM+QM combined. CTA tile 128x256, 256 thr
// (8 warps 2x4, each 64x64 -> MMA:LDSM ratio 4), 2-stage ring, 2 CTAs/SM.
// Output KQ[M,1024] fp16 (+ fp32 bias).
// ===========================================================================
#define TILE_B256 (256 * ROWB)                   // 36864
#define STAGE_KQ (TILE_B + TILE_B256)            // 55296
#define GEMM_SMEM_KQ (2 * STAGE_KQ)              // 110592

__global__ __launch_bounds__(256, 2) void gemm_kq(
    const __half* __restrict__ A, const __half* __restrict__ W,
    const float* __restrict__ bias, __half* __restrict__ outH,
    int M, int N, int K)         // N = 1024
{
    extern __shared__ char smem[];
    const uint32_t sbase = smem_to_u32(smem);
    const int tid = threadIdx.x;
    const int wid = tid >> 5, lane = tid & 31;
    const int bm = blockIdx.y * 128;
    const int bn = blockIdx.x * 256;
    const int wm = wid >> 2, wn = wid & 3;   // 2x4 grid of 64x64 tiles
    const int NCH = K / KC;

    const __half* Ab = A + (size_t)bm * K;
    const __half* Wb = W + (size_t)bn * K;

    auto load_chunk = [&](int kc, int s) {
        uint32_t st = sbase + s * STAGE_KQ;
        int koff = kc * KC;
        #pragma unroll
        for (int j = 0; j < 12; j++) {
            int q = tid + j * 256;           // 0..3071
            const __half* src;
            uint32_t dst;
            if (q < 1024) {                  // A: 128 rows
                int r = q >> 3, seg = q & 7;
                src = Ab + (size_t)r * K + koff + seg * 8;
                dst = st + r * ROWB + seg * 16;
            } else {                         // B: 256 rows
                int q2 = q - 1024;
                int r = q2 >> 3, seg = q2 & 7;
                src = Wb + (size_t)r * K + koff + seg * 8;
                dst = st + TILE_B + r * ROWB + seg * 16;
            }
            asm volatile("cp.async.cg.shared.global [%0], [%1], 16;\n"
                         :: "r"(dst), "l"(src));
        }
        asm volatile("cp.async.commit_group;\n");
    };

    uint32_t acc[4][8][2];
    #pragma unroll
    for (int i = 0; i < 4; i++)
        #pragma unroll
        for (int j = 0; j < 8; j++) { acc[i][j][0] = 0u; acc[i][j][1] = 0u; }

    load_chunk(0, 0);

    const uint32_t a_r = (lane & 15);
    const uint32_t a_k = (lane >> 4) * 16;
    const uint32_t b_r = (lane & 7) + ((lane >> 4) << 3);
    const uint32_t b_k = ((lane >> 3) & 1) * 16;

    for (int i = 0; i < NCH; i++) {
        int s = i & 1;
        __syncthreads();
        if (i + 1 < NCH) {
            load_chunk(i + 1, 1 - s);
            asm volatile("cp.async.wait_group 1;\n" ::: "memory");
        } else {
            asm volatile("cp.async.wait_group 0;\n" ::: "memory");
        }
        __syncthreads();

        uint32_t At = sbase + s * STAGE_KQ;
        uint32_t Wt = At + TILE_B;

        #pragma unroll
        for (int k16 = 0; k16 < 4; k16++) {
            uint32_t a[4][4];
            #pragma unroll
            for (int mi = 0; mi < 4; mi++) {
                uint32_t addr = At + (wm * 64 + mi * 16 + a_r) * ROWB
                              + k16 * 32 + a_k;
                ldsm_x4(a[mi][0], a[mi][1], a[mi][2], a[mi][3], addr);
            }
            uint32_t b[8][2];
            #pragma unroll
            for (int bp = 0; bp < 4; bp++) {
                uint32_t r0, r1, r2, r3;
                uint32_t addr = Wt + (wn * 64 + bp * 16 + b_r) * ROWB
                              + k16 * 32 + b_k;
                ldsm_x4(r0, r1, r2, r3, addr);
                b[2 * bp + 0][0] = r0; b[2 * bp + 0][1] = r1;
                b[2 * bp + 1][0] = r2; b[2 * bp + 1][1] = r3;
            }
            #pragma unroll
            for (int mi = 0; mi < 4; mi++)
                #pragma unroll
                for (int ni = 0; ni < 8; ni++)
                    mma16816h(acc[mi][ni], a[mi], b[ni]);
        }
    }

    const int r0 = bm + wm * 64 + (lane >> 2);
    const int c0 = bn + wn * 64 + (lane & 3) * 2;
    #pragma unroll
    for (int mi = 0; mi < 4; mi++) {
        #pragma unroll
        for (int h = 0; h < 2; h++) {
            int row = r0 + mi * 16 + h * 8;
            #pragma unroll
            for (int ni = 0; ni < 8; ni++) {
                int col = c0 + ni * 8;
                size_t idx = (size_t)row * N + col;
                float2 bv = *(const float2*)(bias + col);
                float2 p = __half22float2(
                    *reinterpret_cast<__half2*>(&acc[mi][ni][h]));
                *(__half2*)(outH + idx) =
                    __floats2half2_rn(p.x + bv.x, p.y + bv.y);
            }
        }
    }
}

// ===========================================================================
// Taylor sincos for tiny delta
// ===========================================================================
__device__ __forceinline__ void sincos_small(float x, float& s, float& c) {
    float x2 = x * x;
    s = x * fmaf(x2, fmaf(x2, fmaf(x2, -1.f / 5040.f, 1.f / 120.f), -1.f / 6.f), 1.f);
    c = fmaf(x2, fmaf(x2, fmaf(x2, -1.f / 720.f, 1.f / 24.f), -0.5f), 1.f);
}

// ===========================================================================
// Fused phasor + chunked cumsum + retrieval + LayerNorm -> fp16. Two barriers.
// KM/QM read from combined KQ[M,1024] (cols 0-511 / 512-1023).
// ===========================================================================
#define CHK 64
#define NW  16

__global__ __launch_bounds__(512) void phasor_ln_kernel(
    const __half* __restrict__ V, const __half* __restrict__ KQ,
    const __half2* __restrict__ cs,
    const float* __restrict__ msp,
    const float* __restrict__ lng, const float* __restrict__ lnb,
    __half* __restrict__ Oh, int S, int D)
{
    const int d = threadIdx.x;
    const int nC = S / CHK;
    const int b = blockIdx.x / nC;
    const int c = blockIdx.x % nC;

    const float ms  = msp[0];
    const float g   = lng[d];
    const float be  = lnb[d];
    const float inv = rsqrtf((float)D);

    const int lane = d & 31;
    const int w    = d >> 5;

    __shared__ float sm1[CHK * 17];
    __shared__ float sm2[CHK * 17];
    __shared__ float smu[CHK];
    __shared__ float srs[CHK];

    float r[CHK];
    float mr = 0.f, mi = 0.f;
    size_t base   = ((size_t)b * S + (size_t)c * CHK) * D + d;
    size_t kqbase = ((size_t)b * S + (size_t)c * CHK) * (2 * D) + d;
    size_t pbase  = ((size_t)c * CHK) * D + d;

    #pragma unroll
    for (int s = 0; s < CHK; s++) {
        size_t idx  = base + (size_t)s * D;
        size_t kqi  = kqbase + (size_t)s * (2 * D);
        size_t pidx = pbase + (size_t)s * D;

        float2 cssb = __half22float2(cs[pidx]);
        float cbp = cssb.x;
        float sbp = cssb.y;
        float dk = __half2float(KQ[kqi]) * ms;
        float dq = __half2float(KQ[kqi + D]) * ms;
        float sk, ck, sq, cq;
        sincos_small(dk, sk, ck);
        sincos_small(dq, sq, cq);

        float ckp = cbp * ck - sbp * sk;
        float skp = sbp * ck + cbp * sk;
        float cqp = cbp * cq - sbp * sq;
        float sqp = sbp * cq + cbp * sq;

        float v = __half2float(V[idx]);
        mr = fmaf(v, ckp, mr);
        mi = fmaf(v, skp, mi);

        float rv = (mr * cqp + mi * sqp) * inv;
        r[s] = rv;

        float s1 = rv, s2 = rv * rv;
        #pragma unroll
        for (int o = 16; o > 0; o >>= 1) {
            s1 += __shfl_xor_sync(0xffffffffu, s1, o);
            s2 += __shfl_xor_sync(0xffffffffu, s2, o);
        }
        if (lane == 0) { sm1[s * 17 + w] = s1; sm2[s * 17 + w] = s2; }
    }
    __syncthreads();

    if (d < CHK) {
        float a1 = 0.f, a2 = 0.f;
        #pragma unroll
        for (int j = 0; j < NW; j++) {
            a1 += sm1[d * 17 + j];
            a2 += sm2[d * 17 + j];
        }
        float mu = a1 / (float)D;
        smu[d] = mu;
        srs[d] = rsqrtf(a2 / (float)D - mu * mu + 1e-5f);
    }
    __syncthreads();

    #pragma unroll
    for (int s = 0; s < CHK; s++) {
        float normed = (r[s] - smu[s]) * srs[s] * g + be;
        Oh[base + (size_t)s * D] = __float2half(normed);
    }
}

// ===========================================================================
// Launch
// ===========================================================================
extern "C" void kernel_launch(void* const* d_in, const int* in_sizes, int n_in,
                              void* d_out, int out_size)
{
    const float* x    = (const float*)d_in[0];
    const float* bp   = (const float*)d_in[1];
    const float* Wk   = (const float*)d_in[2];
    const float* bk   = (const float*)d_in[3];
    const float* Wv   = (const float*)d_in[4];
    const float* bv   = (const float*)d_in[5];
    const float* Wq   = (const float*)d_in[6];
    const float* bq   = (const float*)d_in[7];
    const float* Wkm  = (const float*)d_in[8];
    const float* bkm  = (const float*)d_in[9];
    const float* Wqm  = (const float*)d_in[10];
    const float* bqm  = (const float*)d_in[11];
    const float* ms   = (const float*)d_in[12];
    const float* lng  = (const float*)d_in[13];
    const float* lnb  = (const float*)d_in[14];
    const float* Wo   = (const float*)d_in[15];
    const float* bo   = (const float*)d_in[16];
    float* out = (float*)d_out;

    const int D  = in_sizes[3];         // 512
    const int SD = in_sizes[1];         // S*D
    const int S  = SD / D;              // 4096
    const int M  = in_sizes[0] / D;     // 16384

    __half* hp = nullptr;    cudaGetSymbolAddress((void**)&hp, g_h);
    __half* kqp = nullptr;   cudaGetSymbolAddress((void**)&kqp, g_kq);
    __half* whp = nullptr;   cudaGetSymbolAddress((void**)&whp, g_wh);
    __half2* csb = nullptr;  cudaGetSymbolAddress((void**)&csb, g_cs);
    float* bckq = nullptr;   cudaGetSymbolAddress((void**)&bckq, g_bc);
    float* zerop = nullptr;  cudaGetSymbolAddress((void**)&zerop, g_zero);

    __half* xh  = hp + 0L * MAXELEM;
    __half* NBh = hp + 1L * MAXELEM;
    __half* Vh  = hp + 2L * MAXELEM;

    __half* Wh[6];
    for (int j = 0; j < 6; j++) Wh[j] = whp + (size_t)j * WELEM;
    __half* WkT  = whp + 6L * WELEM;
    __half* WqT  = whp + 7L * WELEM;
    __half* Wckq = whp + 8L * WELEM;        // [1024, 512] (2 WELEM slots)

    cudaFuncSetAttribute(gemm_h, cudaFuncAttributeMaxDynamicSharedMemorySize,
                         GEMM_SMEM_F32);
    cudaFuncSetAttribute(gemm_kq, cudaFuncAttributeMaxDynamicSharedMemorySize,
                         GEMM_SMEM_KQ);

    // ---- launch 0: mega elementwise ----
    MegaArgs ma;
    ma.x = (const float4*)x;
    ma.w[0] = (const float4*)Wk;  ma.w[1] = (const float4*)Wv;
    ma.w[2] = (const float4*)Wq;  ma.w[3] = (const float4*)Wkm;
    ma.w[4] = (const float4*)Wqm; ma.w[5] = (const float4*)Wo;
    ma.xh = (__half2*)xh;
    for (int j = 0; j < 6; j++) ma.wh[j] = (__half2*)Wh[j];
    ma.bp = bp;  ma.cs = csb;
    ma.WkF = Wk; ma.WqF = Wq;
    ma.WkT = WkT; ma.WqT = WqT;
    ma.Wkm = Wkm; ma.Wqm = Wqm;
    ma.bk = bk; ma.bq = bq; ma.bkm = bkm; ma.bqm = bqm;
    ma.bckq = bckq;
    ma.x4 = M * D / 4;
    ma.w4 = WELEM / 4;
    ma.bx  = ma.x4 / 256;
    ma.bw  = ma.bx + 6 * (ma.w4 / 256);
    ma.bt  = ma.bw + SD / 256;
    ma.btr = ma.bt + 512;
    mega_kernel<<<ma.btr + 128, 256>>>(ma);

    // ---- launch 1: V + composite weights (z-jobs, early-exit M) ----
    Job jV  = { xh,    Wh[1], bv,    nullptr, nullptr, Vh, 1, M };
    Job jCk = { Wh[3], WkT,   zerop, nullptr, nullptr, Wckq, 1, D };
    Job jCq = { Wh[4], WqT,   zerop, nullptr, nullptr, Wckq + (size_t)D * D, 1, D };
    dim3 gv(D / 128, M / 128, 3);
    gemm_h<<<gv, 256, GEMM_SMEM_F32>>>(jV, jCk, jCq, D, D);

    // ---- launch 2: KQ = x @ Wckq^T + bckq (fp16 acc, 128x256 tiles) ----
    dim3 gkq(2 * D / 256, M / 128, 1);
    gemm_kq<<<gkq, 256, GEMM_SMEM_KQ>>>(xh, Wckq, bckq, kqp, M, 2 * D, D);

    // ---- launch 3: phasor + cumsum + retrieval + LayerNorm [profiled] ----
    phasor_ln_kernel<<<(M / CHK), D>>>(Vh, kqp, csb, ms, lng, lnb, NBh, S, D);

    // ---- launch 4: out = x + normed@Wo^T + bo ----
    Job jO = { NBh, Wh[5], bo, x, out, nullptr, 2, M };
    dim3 g1(D / 128, M / 128, 1);
    gemm_h<<<g1, 256, GEMM_SMEM_F32>>>(jO, jO, jO, D, D);
}

// round 10
// speedup vs baseline: 1.6470x; 1.0329x over previous
#include <cuda_runtime.h>
#include <cuda_fp16.h>
#include <math.h>
#include <stdint.h>

// ===========================================================================
// Scratch (device globals; no allocation allowed)
// B=4, S=4096, D=512 -> M = 16384
// ===========================================================================
#define MAXELEM (16384 * 512)
#define MAXPH   (4096 * 512)
#define WELEM   (512 * 512)

__device__ __align__(256) __half g_h[3][MAXELEM];     // xh, NBh, Vh
__device__ __align__(256) __half g_kq[2 * MAXELEM];   // KQ: [M, 1024]
__device__ __align__(256) __half g_wh[10][WELEM];     // Wk..Wo, WkT, WqT, Wckq(2)
__device__ __align__(256) __half2 g_cs[MAXPH];        // packed (cos,sin) base phase
__device__ float g_bc[1024];                          // combined composite bias
__device__ float g_zero[512];                         // stays zero (.bss)

// ===========================================================================
// helpers
// ===========================================================================
__device__ __forceinline__ uint32_t smem_to_u32(const void* smem_ptr) {
    uint32_t addr;
    asm("{ .reg .u64 tmp; cvta.to.shared.u64 tmp, %1; cvt.u32.u64 %0, tmp; }"
        : "=r"(addr) : "l"(smem_ptr));
    return addr;
}

__device__ __forceinline__ void ldsm_x4(uint32_t& r0, uint32_t& r1,
                                        uint32_t& r2, uint32_t& r3, uint32_t a) {
    asm volatile("ldmatrix.sync.aligned.m8n8.x4.shared.b16 {%0,%1,%2,%3}, [%4];\n"
                 : "=r"(r0), "=r"(r1), "=r"(r2), "=r"(r3) : "r"(a));
}

__device__ __forceinline__ void mma16816(float* c, const uint32_t* a,
                                         const uint32_t* b) {
    asm volatile(
        "mma.sync.aligned.m16n8k16.row.col.f32.f16.f16.f32 "
        "{%0,%1,%2,%3},{%4,%5,%6,%7},{%8,%9},{%0,%1,%2,%3};\n"
        : "+f"(c[0]), "+f"(c[1]), "+f"(c[2]), "+f"(c[3])
        : "r"(a[0]), "r"(a[1]), "r"(a[2]), "r"(a[3]), "r"(b[0]), "r"(b[1]));
}

__device__ __forceinline__ void mma16816h(uint32_t* c, const uint32_t* a,
                                          const uint32_t* b) {
    asm volatile(
        "mma.sync.aligned.m16n8k16.row.col.f16.f16.f16.f16 "
        "{%0,%1},{%2,%3,%4,%5},{%6,%7},{%0,%1};\n"
        : "+r"(c[0]), "+r"(c[1])
        : "r"(a[0]), "r"(a[1]), "r"(a[2]), "r"(a[3]), "r"(b[0]), "r"(b[1]));
}

// ===========================================================================
// Launch 0: mega elementwise kernel (cvt x + weights, phase table,
// transposes, composite biases)
// ===========================================================================
struct MegaArgs {
    const float4* x;
    const float4* w[6];
    __half2* xh;
    __half2* wh[6];
    const float* bp;
    __half2* cs;
    const float* WkF; const float* WqF;
    __half* WkT; __half* WqT;
    const float* Wkm; const float* Wqm;
    const float* bk; const float* bq;
    const float* bkm; const float* bqm;
    float* bckq;
    int x4, w4;
    int bx, bw, bt, btr;
};

__global__ void mega_kernel(MegaArgs a) {
    int blk = blockIdx.x;
    int tid = threadIdx.x;
    if (blk < a.bx) {
        int j = blk * 256 + tid;
        float4 v = a.x[j];
        a.xh[2 * j + 0] = __floats2half2_rn(v.x, v.y);
        a.xh[2 * j + 1] = __floats2half2_rn(v.z, v.w);
    } else if (blk < a.bw) {
        int q = (blk - a.bx) * 256 + tid;
        int t = q / a.w4;
        int j = q - t * a.w4;
        float4 v = a.w[t][j];
        a.wh[t][2 * j + 0] = __floats2half2_rn(v.x, v.y);
        a.wh[t][2 * j + 1] = __floats2half2_rn(v.z, v.w);
    } else if (blk < a.bt) {
        int j = (blk - a.bw) * 256 + tid;
        float s, c;
        sincosf(a.bp[j], &s, &c);
        a.cs[j] = __floats2half2_rn(c, s);
    } else if (blk < a.btr) {
        __shared__ float sm[32][33];
        int idx = blk - a.bt;
        const float* src = (idx < 256) ? a.WkF : a.WqF;
        __half* dst = (idx < 256) ? a.WkT : a.WqT;
        idx &= 255;
        int tr = idx >> 4, tc = idx & 15;
        int tx = tid & 31, ty = tid >> 5;
        #pragma unroll
        for (int i = 0; i < 4; i++)
            sm[ty + i * 8][tx] = src[(tr * 32 + ty + i * 8) * 512 + tc * 32 + tx];
        __syncthreads();
        #pragma unroll
        for (int i = 0; i < 4; i++)
            dst[(tc * 32 + ty + i * 8) * 512 + tr * 32 + tx] =
                __float2half(sm[tx][ty + i * 8]);
    } else {
        int idx = blk - a.btr;               // 0..127
        int isQ = (idx >= 64);
        const float* Wm = isQ ? a.Wqm : a.Wkm;
        const float* b1 = isQ ? a.bq  : a.bk;
        const float* b2 = isQ ? a.bqm : a.bkm;
        float* bc = a.bckq + (isQ ? 512 : 0);
        int row = (idx & 63) * 8 + (tid >> 5);
        int lane = tid & 31;
        float s = 0.f;
        #pragma unroll
        for (int j = 0; j < 16; j++)
            s += Wm[row * 512 + lane + 32 * j] * b1[lane + 32 * j];
        #pragma unroll
        for (int o = 16; o > 0; o >>= 1)
            s += __shfl_xor_sync(0xffffffffu, s, o);
        if (lane == 0) bc[row] = s + b2[row];
    }
}

// ===========================================================================
// GEMM common
// ===========================================================================
#define KC 64
#define ROWB 144
#define TILE_B (128 * ROWB)             // 18432

struct Job {
    const __half* A;
    const __half* W;
    const float*  bias;
    const float*  resid;
    float*        outF;
    __half*       outH;
    int           mode;
    int           Mj;      // rows of this job (bm >= Mj -> idle CTA)
};

// ===========================================================================
// fp32-accumulate GEMM (V, composite, out). 128x128 tile, 256 thr,
// 2 CTAs/SM, 3-stage ring. mode 1: fp16 out; mode 2: fp32 out + resid.
// ===========================================================================
#define STAGE_F32 (2 * TILE_B)              // 36864
#define GEMM_SMEM_F32 (3 * STAGE_F32)       // 110592

__global__ __launch_bounds__(256, 2) void gemm_h(
    Job j0, Job j1, Job j2, int N, int K)
{
    extern __shared__ char smem[];
    const Job jb = (blockIdx.z == 0) ? j0 : (blockIdx.z == 1) ? j1 : j2;

    const int bm = blockIdx.y * 128;
    if (bm >= jb.Mj) return;
    const int bn = blockIdx.x * 128;

    const uint32_t sbase = smem_to_u32(smem);
    const int tid = threadIdx.x;
    const int wid = tid >> 5, lane = tid & 31;
    const int wm = wid >> 2, wn = wid & 3;
    const int NCH = K / KC;

    const __half* Ab = jb.A + (size_t)bm * K;
    const __half* Wb = jb.W + (size_t)bn * K;

    auto load_chunk = [&](int kc, int s) {
        uint32_t st = sbase + s * STAGE_F32;
        int koff = kc * KC;
        #pragma unroll
        for (int j = 0; j < 8; j++) {
            int q = tid + j * 256;
            int t = q >> 10;
            int r = (q >> 3) & 127;
            int seg = q & 7;
            const __half* src = (t ? Wb : Ab) + (size_t)r * K + koff + seg * 8;
            uint32_t dst = st + t * TILE_B + r * ROWB + seg * 16;
            asm volatile("cp.async.cg.shared.global [%0], [%1], 16;\n"
                         :: "r"(dst), "l"(src));
        }
        asm volatile("cp.async.commit_group;\n");
    };

    float acc[4][4][4];
    #pragma unroll
    for (int i = 0; i < 4; i++)
        #pragma unroll
        for (int j = 0; j < 4; j++)
            #pragma unroll
            for (int e = 0; e < 4; e++) acc[i][j][e] = 0.f;

    load_chunk(0, 0);
    load_chunk(1, 1);

    const uint32_t a_r = (lane & 15);
    const uint32_t a_k = (lane >> 4) * 16;
    const uint32_t b_r = (lane & 7) + ((lane >> 4) << 3);
    const uint32_t b_k = ((lane >> 3) & 1) * 16;

    for (int i = 0; i < NCH; i++) {
        int s = i % 3;
        if (i == NCH - 1)
            asm volatile("cp.async.wait_group 0;\n" ::: "memory");
        else
            asm volatile("cp.async.wait_group 1;\n" ::: "memory");
        __syncthreads();
        if (i + 2 < NCH) load_chunk(i + 2, (i + 2) % 3);

        uint32_t At = sbase + s * STAGE_F32;
        uint32_t Wt = At + TILE_B;

        #pragma unroll
        for (int k16 = 0; k16 < 4; k16++) {
            uint32_t a[4][4];
            #pragma unroll
            for (int mi = 0; mi < 4; mi++) {
                uint32_t addr = At + (wm * 64 + mi * 16 + a_r) * ROWB
                              + k16 * 32 + a_k;
                ldsm_x4(a[mi][0], a[mi][1], a[mi][2], a[mi][3], addr);
            }
            uint32_t b[4][2];
            #pragma unroll
            for (int bp = 0; bp < 2; bp++) {
                uint32_t r0, r1, r2, r3;
                uint32_t addr = Wt + (wn * 32 + bp * 16 + b_r) * ROWB
                              + k16 * 32 + b_k;
                ldsm_x4(r0, r1, r2, r3, addr);
                b[2 * bp + 0][0] = r0; b[2 * bp + 0][1] = r1;
                b[2 * bp + 1][0] = r2; b[2 * bp + 1][1] = r3;
            }
            #pragma unroll
            for (int mi = 0; mi < 4; mi++)
                #pragma unroll
                for (int ni = 0; ni < 4; ni++)
                    mma16816(acc[mi][ni], a[mi], b[ni]);
        }
    }

    const int r0 = bm + wm * 64 + (lane >> 2);
    const int c0 = bn + wn * 32 + (lane & 3) * 2;
    const int mode = jb.mode;
    float2 bv[4];
    #pragma unroll
    for (int ni = 0; ni < 4; ni++)
        bv[ni] = *(const float2*)(jb.bias + c0 + ni * 8);
    #pragma unroll
    for (int mi = 0; mi < 4; mi++) {
        #pragma unroll
        for (int h = 0; h < 2; h++) {
            int row = r0 + mi * 16 + h * 8;
            #pragma unroll
            for (int ni = 0; ni < 4; ni++) {
                int col = c0 + ni * 8;
                size_t idx = (size_t)row * N + col;
                float v0 = acc[mi][ni][2 * h + 0] + bv[ni].x;
                float v1 = acc[mi][ni][2 * h + 1] + bv[ni].y;
                if (mode == 2) {
                    float2 rv = *(const float2*)(jb.resid + idx);
                    v0 += rv.x; v1 += rv.y;
                    float2 o; o.x = v0; o.y = v1;
                    *(float2*)(jb.outF + idx) = o;
                } else {
                    *(__half2*)(jb.outH + idx) = __floats2half2_rn(v0, v1);
                }
            }
        }
    }
}

// ===========================================================================
// fp16-accumulate GEMM for KM+QM combined. CTA tile 128x256, 256 thr
// (8 warps 2x4, each 64x64), 2-stage ring, 2 CTAs/SM. KQ[M,1024] fp16.
// ===========================================================================
#define TILE_B256 (256 * ROWB)                   // 36864
#define STAGE_KQ (TILE_B + TILE_B256)            // 55296
#define GEMM_SMEM_KQ (2 * STAGE_KQ)              // 110592

__global__ __launch_bounds__(256, 2) void gemm_kq(
    const __half* __restrict__ A, const __half* __restrict__ W,
    const float* __restrict__ bias, __half* __restrict__ outH,
    int M, int N, int K)         // N = 1024
{
    extern __shared__ char smem[];
    const uint32_t sbase = smem_to_u32(smem);
    const int tid = threadIdx.x;
    const int wid = tid >> 5, lane = tid & 31;
    const int bm = blockIdx.y * 128;
    const int bn = blockIdx.x * 256;
    const int wm = wid >> 2, wn = wid & 3;
    const int NCH = K / KC;

    const __half* Ab = A + (size_t)bm * K;
    const __half* Wb = W + (size_t)bn * K;

    auto load_chunk = [&](int kc, int s) {
        uint32_t st = sbase + s * STAGE_KQ;
        int koff = kc * KC;
        #pragma unroll
        for (int j = 0; j < 12; j++) {
            int q = tid + j * 256;
            const __half* src;
            uint32_t dst;
            if (q < 1024) {
                int r = q >> 3, seg = q & 7;
                src = Ab + (size_t)r * K + koff + seg * 8;
                dst = st + r * ROWB + seg * 16;
            } else {
                int q2 = q - 1024;
                int r = q2 >> 3, seg = q2 & 7;
                src = Wb + (size_t)r * K + koff + seg * 8;
                dst = st + TILE_B + r * ROWB + seg * 16;
            }
            asm volatile("cp.async.cg.shared.global [%0], [%1], 16;\n"
                         :: "r"(dst), "l"(src));
        }
        asm volatile("cp.async.commit_group;\n");
    };

    uint32_t acc[4][8][2];
    #pragma unroll
    for (int i = 0; i < 4; i++)
        #pragma unroll
        for (int j = 0; j < 8; j++) { acc[i][j][0] = 0u; acc[i][j][1] = 0u; }

    load_chunk(0, 0);

    const uint32_t a_r = (lane & 15);
    const uint32_t a_k = (lane >> 4) * 16;
    const uint32_t b_r = (lane & 7) + ((lane >> 4) << 3);
    const uint32_t b_k = ((lane >> 3) & 1) * 16;

    for (int i = 0; i < NCH; i++) {
        int s = i & 1;
        __syncthreads();
        if (i + 1 < NCH) {
            load_chunk(i + 1, 1 - s);
            asm volatile("cp.async.wait_group 1;\n" ::: "memory");
        } else {
            asm volatile("cp.async.wait_group 0;\n" ::: "memory");
        }
        __syncthreads();

        uint32_t At = sbase + s * STAGE_KQ;
        uint32_t Wt = At + TILE_B;

        #pragma unroll
        for (int k16 = 0; k16 < 4; k16++) {
            uint32_t a[4][4];
            #pragma unroll
            for (int mi = 0; mi < 4; mi++) {
                uint32_t addr = At + (wm * 64 + mi * 16 + a_r) * ROWB
                              + k16 * 32 + a_k;
                ldsm_x4(a[mi][0], a[mi][1], a[mi][2], a[mi][3], addr);
            }
            uint32_t b[8][2];
            #pragma unroll
            for (int bp = 0; bp < 4; bp++) {
                uint32_t r0, r1, r2, r3;
                uint32_t addr = Wt + (wn * 64 + bp * 16 + b_r) * ROWB
                              + k16 * 32 + b_k;
                ldsm_x4(r0, r1, r2, r3, addr);
                b[2 * bp + 0][0] = r0; b[2 * bp + 0][1] = r1;
                b[2 * bp + 1][0] = r2; b[2 * bp + 1][1] = r3;
            }
            #pragma unroll
            for (int mi = 0; mi < 4; mi++)
                #pragma unroll
                for (int ni = 0; ni < 8; ni++)
                    mma16816h(acc[mi][ni], a[mi], b[ni]);
        }
    }

    const int r0 = bm + wm * 64 + (lane >> 2);
    const int c0 = bn + wn * 64 + (lane & 3) * 2;
    #pragma unroll
    for (int mi = 0; mi < 4; mi++) {
        #pragma unroll
        for (int h = 0; h < 2; h++) {
            int row = r0 + mi * 16 + h * 8;
            #pragma unroll
            for (int ni = 0; ni < 8; ni++) {
                int col = c0 + ni * 8;
                size_t idx = (size_t)row * N + col;
                float2 bv = *(const float2*)(bias + col);
                float2 p = __half22float2(
                    *reinterpret_cast<__half2*>(&acc[mi][ni][h]));
                *(__half2*)(outH + idx) =
                    __floats2half2_rn(p.x + bv.x, p.y + bv.y);
            }
        }
    }
}

// ===========================================================================
// Taylor sincos for tiny delta
// ===========================================================================
__device__ __forceinline__ void sincos_small(float x, float& s, float& c) {
    float x2 = x * x;
    s = x * fmaf(x2, fmaf(x2, fmaf(x2, -1.f / 5040.f, 1.f / 120.f), -1.f / 6.f), 1.f);
    c = fmaf(x2, fmaf(x2, fmaf(x2, -1.f / 720.f, 1.f / 24.f), -0.5f), 1.f);
}

// ===========================================================================
// Fused phasor + chunked cumsum + retrieval + LayerNorm -> fp16.
// 256 threads, each owns features d=2t, 2t+1 (vectorized half2 I/O, 2-way
// ILP on the serial cumsum chain). Retrieval values cached as half2 in
// registers. 2 CTAs/SM -> 256 blocks in ONE wave. Two block barriers.
// ===========================================================================
#define CHK 64
#define PNW 8     // warps per block

__global__ __launch_bounds__(256, 2) void phasor_ln_kernel(
    const __half* __restrict__ V, const __half* __restrict__ KQ,
    const __half2* __restrict__ cs,
    const float* __restrict__ msp,
    const float* __restrict__ lng, const float* __restrict__ lnb,
    __half* __restrict__ Oh, int S, int D)
{
    const int t = threadIdx.x;          // 0..255
    const int d0 = 2 * t;
    const int nC = S / CHK;
    const int b = blockIdx.x / nC;
    const int c = blockIdx.x % nC;

    const float ms  = msp[0];
    const float2 g  = *(const float2*)(lng + d0);
    const float2 be = *(const float2*)(lnb + d0);
    const float inv = rsqrtf((float)D);

    const int lane = t & 31;
    const int w    = t >> 5;

    __shared__ float sm1[CHK * (PNW + 1)];
    __shared__ float sm2[CHK * (PNW + 1)];
    __shared__ float smu[CHK];
    __shared__ float srs[CHK];

    __half2 rh[CHK];
    float mr0 = 0.f, mi0 = 0.f, mr1 = 0.f, mi1 = 0.f;
    size_t base   = ((size_t)b * S + (size_t)c * CHK) * D + d0;
    size_t kqbase = ((size_t)b * S + (size_t)c * CHK) * (2 * D) + d0;
    size_t pbase  = ((size_t)c * CHK) * D + d0;

    #pragma unroll
    for (int s = 0; s < CHK; s++) {
        size_t idx  = base + (size_t)s * D;
        size_t kqi  = kqbase + (size_t)s * (2 * D);
        size_t pidx = pbase + (size_t)s * D;

        // packed loads: 2 features per thread
        float2 cs2raw = *(const float2*)(cs + pidx);   // two half2s
        __half2 csa = *reinterpret_cast<__half2*>(&cs2raw.x);
        __half2 csb = *reinterpret_cast<__half2*>(&cs2raw.y);
        float2 km = __half22float2(*(const __half2*)(KQ + kqi));
        float2 qm = __half22float2(*(const __half2*)(KQ + kqi + D));
        float2 v2 = __half22float2(*(const __half2*)(V + idx));

        float2 c0f = __half22float2(csa);   // (cos, sin) for d0
        float2 c1f = __half22float2(csb);   // (cos, sin) for d0+1

        float sk0, ck0, sq0, cq0, sk1, ck1, sq1, cq1;
        sincos_small(km.x * ms, sk0, ck0);
        sincos_small(qm.x * ms, sq0, cq0);
        sincos_small(km.y * ms, sk1, ck1);
        sincos_small(qm.y * ms, sq1, cq1);

        // angle addition, lane 0
        float ckp0 = c0f.x * ck0 - c0f.y * sk0;
        float skp0 = c0f.y * ck0 + c0f.x * sk0;
        float cqp0 = c0f.x * cq0 - c0f.y * sq0;
        float sqp0 = c0f.y * cq0 + c0f.x * sq0;
        // lane 1
        float ckp1 = c1f.x * ck1 - c1f.y * sk1;
        float skp1 = c1f.y * ck1 + c1f.x * sk1;
        float cqp1 = c1f.x * cq1 - c1f.y * sq1;
        float sqp1 = c1f.y * cq1 + c1f.x * sq1;

        mr0 = fmaf(v2.x, ckp0, mr0);
        mi0 = fmaf(v2.x, skp0, mi0);
        mr1 = fmaf(v2.y, ckp1, mr1);
        mi1 = fmaf(v2.y, skp1, mi1);

        float rv0 = (mr0 * cqp0 + mi0 * sqp0) * inv;
        float rv1 = (mr1 * cqp1 + mi1 * sqp1) * inv;
        rh[s] = __floats2half2_rn(rv0, rv1);

        float s1 = rv0 + rv1;
        float s2 = rv0 * rv0 + rv1 * rv1;
        #pragma unroll
        for (int o = 16; o > 0; o >>= 1) {
            s1 += __shfl_xor_sync(0xffffffffu, s1, o);
            s2 += __shfl_xor_sync(0xffffffffu, s2, o);
        }
        if (lane == 0) {
            sm1[s * (PNW + 1) + w] = s1;
            sm2[s * (PNW + 1) + w] = s2;
        }
    }
    __syncthreads();

    if (t < CHK) {
        float a1 = 0.f, a2 = 0.f;
        #pragma unroll
        for (int j = 0; j < PNW; j++) {
            a1 += sm1[t * (PNW + 1) + j];
            a2 += sm2[t * (PNW + 1) + j];
        }
        float mu = a1 / (float)D;
        smu[t] = mu;
        srs[t] = rsqrtf(a2 / (float)D - mu * mu + 1e-5f);
    }
    __syncthreads();

    #pragma unroll
    for (int s = 0; s < CHK; s++) {
        float2 rr = __half22float2(rh[s]);
        float mu = smu[s], rstd = srs[s];
        float n0 = (rr.x - mu) * rstd * g.x + be.x;
        float n1 = (rr.y - mu) * rstd * g.y + be.y;
        *(__half2*)(Oh + base + (size_t)s * D) = __floats2half2_rn(n0, n1);
    }
}

// ===========================================================================
// Launch
// ===========================================================================
extern "C" void kernel_launch(void* const* d_in, const int* in_sizes, int n_in,
                              void* d_out, int out_size)
{
    const float* x    = (const float*)d_in[0];
    const float* bp   = (const float*)d_in[1];
    const float* Wk   = (const float*)d_in[2];
    const float* bk   = (const float*)d_in[3];
    const float* Wv   = (const float*)d_in[4];
    const float* bv   = (const float*)d_in[5];
    const float* Wq   = (const float*)d_in[6];
    const float* bq   = (const float*)d_in[7];
    const float* Wkm  = (const float*)d_in[8];
    const float* bkm  = (const float*)d_in[9];
    const float* Wqm  = (const float*)d_in[10];
    const float* bqm  = (const float*)d_in[11];
    const float* ms   = (const float*)d_in[12];
    const float* lng  = (const float*)d_in[13];
    const float* lnb  = (const float*)d_in[14];
    const float* Wo   = (const float*)d_in[15];
    const float* bo   = (const float*)d_in[16];
    float* out = (float*)d_out;

    const int D  = in_sizes[3];         // 512
    const int SD = in_sizes[1];         // S*D
    const int S  = SD / D;              // 4096
    const int M  = in_sizes[0] / D;     // 16384

    __half* hp = nullptr;    cudaGetSymbolAddress((void**)&hp, g_h);
    __half* kqp = nullptr;   cudaGetSymbolAddress((void**)&kqp, g_kq);
    __half* whp = nullptr;   cudaGetSymbolAddress((void**)&whp, g_wh);
    __half2* csb = nullptr;  cudaGetSymbolAddress((void**)&csb, g_cs);
    float* bckq = nullptr;   cudaGetSymbolAddress((void**)&bckq, g_bc);
    float* zerop = nullptr;  cudaGetSymbolAddress((void**)&zerop, g_zero);

    __half* xh  = hp + 0L * MAXELEM;
    __half* NBh = hp + 1L * MAXELEM;
    __half* Vh  = hp + 2L * MAXELEM;

    __half* Wh[6];
    for (int j = 0; j < 6; j++) Wh[j] = whp + (size_t)j * WELEM;
    __half* WkT  = whp + 6L * WELEM;
    __half* WqT  = whp + 7L * WELEM;
    __half* Wckq = whp + 8L * WELEM;        // [1024, 512]

    cudaFuncSetAttribute(gemm_h, cudaFuncAttributeMaxDynamicSharedMemorySize,
                         GEMM_SMEM_F32);
    cudaFuncSetAttribute(gemm_kq, cudaFuncAttributeMaxDynamicSharedMemorySize,
                         GEMM_SMEM_KQ);

    // ---- launch 0: mega elementwise ----
    MegaArgs ma;
    ma.x = (const float4*)x;
    ma.w[0] = (const float4*)Wk;  ma.w[1] = (const float4*)Wv;
    ma.w[2] = (const float4*)Wq;  ma.w[3] = (const float4*)Wkm;
    ma.w[4] = (const float4*)Wqm; ma.w[5] = (const float4*)Wo;
    ma.xh = (__half2*)xh;
    for (int j = 0; j < 6; j++) ma.wh[j] = (__half2*)Wh[j];
    ma.bp = bp;  ma.cs = csb;
    ma.WkF = Wk; ma.WqF = Wq;
    ma.WkT = WkT; ma.WqT = WqT;
    ma.Wkm = Wkm; ma.Wqm = Wqm;
    ma.bk = bk; ma.bq = bq; ma.bkm = bkm; ma.bqm = bqm;
    ma.bckq = bckq;
    ma.x4 = M * D / 4;
    ma.w4 = WELEM / 4;
    ma.bx  = ma.x4 / 256;
    ma.bw  = ma.bx + 6 * (ma.w4 / 256);
    ma.bt  = ma.bw + SD / 256;
    ma.btr = ma.bt + 512;
    mega_kernel<<<ma.btr + 128, 256>>>(ma);

    // ---- launch 1: V + composite weights (z-jobs, early-exit M) ----
    Job jV  = { xh,    Wh[1], bv,    nullptr, nullptr, Vh, 1, M };
    Job jCk = { Wh[3], WkT,   zerop, nullptr, nullptr, Wckq, 1, D };
    Job jCq = { Wh[4], WqT,   zerop, nullptr, nullptr, Wckq + (size_t)D * D, 1, D };
    dim3 gv(D / 128, M / 128, 3);
    gemm_h<<<gv, 256, GEMM_SMEM_F32>>>(jV, jCk, jCq, D, D);

    // ---- launch 2: KQ = x @ Wckq^T + bckq (fp16 acc, 128x256 tiles) ----
    dim3 gkq(2 * D / 256, M / 128, 1);
    gemm_kq<<<gkq, 256, GEMM_SMEM_KQ>>>(xh, Wckq, bckq, kqp, M, 2 * D, D);

    // ---- launch 3: phasor + cumsum + retrieval + LayerNorm [profiled] ----
    phasor_ln_kernel<<<(M / CHK), 256>>>(Vh, kqp, csb, ms, lng, lnb, NBh, S, D);

    // ---- launch 4: out = x + normed@Wo^T + bo ----
    Job jO = { NBh, Wh[5], bo, x, out, nullptr, 2, M };
    dim3 g1(D / 128, M / 128, 1);
    gemm_h<<<g1, 256, GEMM_SMEM_F32>>>(jO, jO, jO, D, D);
}